// round 1
// baseline (speedup 1.0000x reference)
#include <cuda_runtime.h>
#include <math.h>

#define B_ 2
#define S_ 2048
#define E_ 1024
#define H_ 16
#define D_ 64
#define M_ (B_*S_)   // 4096 rows for all projection GEMMs

// Scratch (allocation-free rule: __device__ globals)
__device__ float g_Q[B_*S_*E_];
__device__ float g_K[B_*S_*E_];
__device__ float g_V[B_*S_*E_];
__device__ float g_C[B_*S_*E_];

// ---------------------------------------------------------------------------
// SGEMM (NT): C[M,N] = A[M,K] * B[N,K]^T   (both operands K-contiguous)
// 128x128 block tile, K-tile 16, 256 threads, 8x8 microtile.
// ---------------------------------------------------------------------------
__global__ __launch_bounds__(256, 2)
void sgemm_nt(const float* __restrict__ A, const float* __restrict__ Bw,
              float* __restrict__ C, int M, int N, int K)
{
    __shared__ float As[16][128];   // [k][m] transposed
    __shared__ float Bs[16][128];   // [k][n] transposed

    const int tid = threadIdx.x;
    const int bm = blockIdx.y * 128;
    const int bn = blockIdx.x * 128;
    const int tm = (tid >> 4) << 3;   // 0..120
    const int tn = (tid & 15) << 3;   // 0..120

    float acc[8][8] = {};

    for (int k0 = 0; k0 < K; k0 += 16) {
        #pragma unroll
        for (int l = 0; l < 2; l++) {
            int idx = tid + l * 256;          // 0..511
            int row = idx >> 2;               // 0..127
            int kq  = (idx & 3) << 2;         // 0,4,8,12
            float4 a = *reinterpret_cast<const float4*>(A + (size_t)(bm + row) * K + k0 + kq);
            As[kq+0][row] = a.x; As[kq+1][row] = a.y;
            As[kq+2][row] = a.z; As[kq+3][row] = a.w;
            float4 b = *reinterpret_cast<const float4*>(Bw + (size_t)(bn + row) * K + k0 + kq);
            Bs[kq+0][row] = b.x; Bs[kq+1][row] = b.y;
            Bs[kq+2][row] = b.z; Bs[kq+3][row] = b.w;
        }
        __syncthreads();

        #pragma unroll
        for (int kk = 0; kk < 16; kk++) {
            float a[8], b[8];
            *reinterpret_cast<float4*>(&a[0]) = *reinterpret_cast<float4*>(&As[kk][tm]);
            *reinterpret_cast<float4*>(&a[4]) = *reinterpret_cast<float4*>(&As[kk][tm + 4]);
            *reinterpret_cast<float4*>(&b[0]) = *reinterpret_cast<float4*>(&Bs[kk][tn]);
            *reinterpret_cast<float4*>(&b[4]) = *reinterpret_cast<float4*>(&Bs[kk][tn + 4]);
            #pragma unroll
            for (int i = 0; i < 8; i++)
                #pragma unroll
                for (int j = 0; j < 8; j++)
                    acc[i][j] = fmaf(a[i], b[j], acc[i][j]);
        }
        __syncthreads();
    }

    #pragma unroll
    for (int i = 0; i < 8; i++) {
        float* cp = C + (size_t)(bm + tm + i) * N + bn + tn;
        *reinterpret_cast<float4*>(cp)     = make_float4(acc[i][0], acc[i][1], acc[i][2], acc[i][3]);
        *reinterpret_cast<float4*>(cp + 4) = make_float4(acc[i][4], acc[i][5], acc[i][6], acc[i][7]);
    }
}

// ---------------------------------------------------------------------------
// Flash attention, fp32, causal, per-(b,h,q-tile) block.
// BM=BN=64, 256 threads (16x16), 4x4 microtile. Q/K in smem transposed
// ([d][row]) for conflict-free LDS.128 in the S-gemm; V and P row-major.
// Online softmax: 1 row handled by a quad of threads (shfl reductions).
// NOTE: reference multiplies scores by sqrt(d)=8 (faithful to source).
// ---------------------------------------------------------------------------
#define NEGINF (-1e30f)

__global__ __launch_bounds__(256)
void flash_fwd(const float* __restrict__ Q, const float* __restrict__ K,
               const float* __restrict__ V, float* __restrict__ O)
{
    extern __shared__ float sm[];
    float* Qs  = sm;                  // [64][64]  (k-major / transposed)
    float* Ks  = Qs + 64 * 64;        // [64][64]  (k-major / transposed)
    float* Vs  = Ks + 64 * 64;        // [64][64]  (row-major)
    float* Ps  = Vs + 64 * 64;        // [64][64]  (row-major)
    float* m_s = Ps + 64 * 64;        // [64]
    float* l_s = m_s + 64;            // [64]
    float* a_s = l_s + 64;            // [64]

    const int tid = threadIdx.x;
    const int qt = blockIdx.x, h = blockIdx.y, b = blockIdx.z;
    const size_t base = (size_t)b * S_ * E_ + (size_t)h * D_;

    const int tx = tid & 15, ty = tid >> 4;
    const int r0 = ty << 2, c0 = tx << 2;

    // Load Q tile (transposed into smem). One-time cost per block.
    #pragma unroll
    for (int l = 0; l < 4; l++) {
        int idx = tid + l * 256;          // 0..1023 float4s
        int row = idx >> 4;               // 0..63
        int cq  = (idx & 15) << 2;        // 0..60
        float4 v = *reinterpret_cast<const float4*>(Q + base + (size_t)(qt * 64 + row) * E_ + cq);
        Qs[(cq + 0) * 64 + row] = v.x; Qs[(cq + 1) * 64 + row] = v.y;
        Qs[(cq + 2) * 64 + row] = v.z; Qs[(cq + 3) * 64 + row] = v.w;
    }
    if (tid < 64) { m_s[tid] = NEGINF; l_s[tid] = 0.0f; }

    float o[4][4] = {};
    __syncthreads();

    const float scale = 8.0f;  // * sqrt(HEAD_DIM), faithful to reference

    for (int jt = 0; jt <= qt; jt++) {
        // Load K (transposed) and V (row-major) tiles
        #pragma unroll
        for (int l = 0; l < 4; l++) {
            int idx = tid + l * 256;
            int row = idx >> 4;
            int cq  = (idx & 15) << 2;
            const float* gk = K + base + (size_t)(jt * 64 + row) * E_ + cq;
            float4 kv = *reinterpret_cast<const float4*>(gk);
            Ks[(cq + 0) * 64 + row] = kv.x; Ks[(cq + 1) * 64 + row] = kv.y;
            Ks[(cq + 2) * 64 + row] = kv.z; Ks[(cq + 3) * 64 + row] = kv.w;
            *reinterpret_cast<float4*>(&Vs[row * 64 + cq]) =
                *reinterpret_cast<const float4*>(V + base + (size_t)(jt * 64 + row) * E_ + cq);
        }
        __syncthreads();

        // S = Q K^T (4x4 microtile), conflict-free LDS.128 on both operands
        float s[4][4] = {};
        #pragma unroll
        for (int k = 0; k < 64; k++) {
            float4 qf = *reinterpret_cast<float4*>(&Qs[k * 64 + r0]);
            float4 kf = *reinterpret_cast<float4*>(&Ks[k * 64 + c0]);
            s[0][0] = fmaf(qf.x, kf.x, s[0][0]); s[0][1] = fmaf(qf.x, kf.y, s[0][1]);
            s[0][2] = fmaf(qf.x, kf.z, s[0][2]); s[0][3] = fmaf(qf.x, kf.w, s[0][3]);
            s[1][0] = fmaf(qf.y, kf.x, s[1][0]); s[1][1] = fmaf(qf.y, kf.y, s[1][1]);
            s[1][2] = fmaf(qf.y, kf.z, s[1][2]); s[1][3] = fmaf(qf.y, kf.w, s[1][3]);
            s[2][0] = fmaf(qf.z, kf.x, s[2][0]); s[2][1] = fmaf(qf.z, kf.y, s[2][1]);
            s[2][2] = fmaf(qf.z, kf.z, s[2][2]); s[2][3] = fmaf(qf.z, kf.w, s[2][3]);
            s[3][0] = fmaf(qf.w, kf.x, s[3][0]); s[3][1] = fmaf(qf.w, kf.y, s[3][1]);
            s[3][2] = fmaf(qf.w, kf.z, s[3][2]); s[3][3] = fmaf(qf.w, kf.w, s[3][3]);
        }

        // Scale + causal mask, stash into Ps (vectorized stores)
        #pragma unroll
        for (int i = 0; i < 4; i++) {
            int qi = qt * 64 + r0 + i;
            int kj = jt * 64 + c0;
            float4 w;
            w.x = (kj + 0 <= qi) ? s[i][0] * scale : NEGINF;
            w.y = (kj + 1 <= qi) ? s[i][1] * scale : NEGINF;
            w.z = (kj + 2 <= qi) ? s[i][2] * scale : NEGINF;
            w.w = (kj + 3 <= qi) ? s[i][3] * scale : NEGINF;
            *reinterpret_cast<float4*>(&Ps[(r0 + i) * 64 + c0]) = w;
        }
        __syncthreads();

        // Online softmax: quad (4 consecutive threads) per row, 16 cols each
        {
            int row = tid >> 2;
            int cb  = (tid & 3) << 4;
            float mx = NEGINF;
            #pragma unroll
            for (int c = 0; c < 16; c += 4) {
                float4 p = *reinterpret_cast<float4*>(&Ps[row * 64 + cb + c]);
                mx = fmaxf(mx, fmaxf(fmaxf(p.x, p.y), fmaxf(p.z, p.w)));
            }
            mx = fmaxf(mx, __shfl_xor_sync(0xffffffffu, mx, 1));
            mx = fmaxf(mx, __shfl_xor_sync(0xffffffffu, mx, 2));
            float m_old = m_s[row];
            float m_new = fmaxf(m_old, mx);
            float sum = 0.0f;
            #pragma unroll
            for (int c = 0; c < 16; c += 4) {
                float4 p = *reinterpret_cast<float4*>(&Ps[row * 64 + cb + c]);
                p.x = __expf(p.x - m_new); p.y = __expf(p.y - m_new);
                p.z = __expf(p.z - m_new); p.w = __expf(p.w - m_new);
                sum += (p.x + p.y) + (p.z + p.w);
                *reinterpret_cast<float4*>(&Ps[row * 64 + cb + c]) = p;
            }
            sum += __shfl_xor_sync(0xffffffffu, sum, 1);
            sum += __shfl_xor_sync(0xffffffffu, sum, 2);
            if ((tid & 3) == 0) {
                float alpha = __expf(m_old - m_new);
                l_s[row] = l_s[row] * alpha + sum;
                m_s[row] = m_new;
                a_s[row] = alpha;
            }
        }
        __syncthreads();

        // O = O*alpha + P V  (4x4 microtile)
        #pragma unroll
        for (int i = 0; i < 4; i++) {
            float a = a_s[r0 + i];
            o[i][0] *= a; o[i][1] *= a; o[i][2] *= a; o[i][3] *= a;
        }
        #pragma unroll
        for (int k = 0; k < 64; k++) {
            float4 vf = *reinterpret_cast<float4*>(&Vs[k * 64 + c0]);
            float p0 = Ps[(r0 + 0) * 64 + k];
            float p1 = Ps[(r0 + 1) * 64 + k];
            float p2 = Ps[(r0 + 2) * 64 + k];
            float p3 = Ps[(r0 + 3) * 64 + k];
            o[0][0] = fmaf(p0, vf.x, o[0][0]); o[0][1] = fmaf(p0, vf.y, o[0][1]);
            o[0][2] = fmaf(p0, vf.z, o[0][2]); o[0][3] = fmaf(p0, vf.w, o[0][3]);
            o[1][0] = fmaf(p1, vf.x, o[1][0]); o[1][1] = fmaf(p1, vf.y, o[1][1]);
            o[1][2] = fmaf(p1, vf.z, o[1][2]); o[1][3] = fmaf(p1, vf.w, o[1][3]);
            o[2][0] = fmaf(p2, vf.x, o[2][0]); o[2][1] = fmaf(p2, vf.y, o[2][1]);
            o[2][2] = fmaf(p2, vf.z, o[2][2]); o[2][3] = fmaf(p2, vf.w, o[2][3]);
            o[3][0] = fmaf(p3, vf.x, o[3][0]); o[3][1] = fmaf(p3, vf.y, o[3][1]);
            o[3][2] = fmaf(p3, vf.z, o[3][2]); o[3][3] = fmaf(p3, vf.w, o[3][3]);
        }
        __syncthreads();
    }

    // Normalize and write ctx in [B, S, E] layout (head slice at h*64)
    #pragma unroll
    for (int i = 0; i < 4; i++) {
        float inv = 1.0f / l_s[r0 + i];
        float4 w = make_float4(o[i][0] * inv, o[i][1] * inv, o[i][2] * inv, o[i][3] * inv);
        *reinterpret_cast<float4*>(O + base + (size_t)(qt * 64 + r0 + i) * E_ + c0) = w;
    }
}

// ---------------------------------------------------------------------------
// Launch: QKV projections -> flash attention -> output projection.
// All on the capture stream, dependency via stream order.
// ---------------------------------------------------------------------------
extern "C" void kernel_launch(void* const* d_in, const int* in_sizes, int n_in,
                              void* d_out, int out_size)
{
    const float* x  = (const float*)d_in[0];
    const float* Wq = (const float*)d_in[1];
    const float* Wk = (const float*)d_in[2];
    const float* Wv = (const float*)d_in[3];
    const float* Wo = (const float*)d_in[4];
    float* out = (float*)d_out;

    float *q, *k, *v, *c;
    cudaGetSymbolAddress((void**)&q, g_Q);
    cudaGetSymbolAddress((void**)&k, g_K);
    cudaGetSymbolAddress((void**)&v, g_V);
    cudaGetSymbolAddress((void**)&c, g_C);

    const size_t shm = (size_t)(4 * 64 * 64 + 3 * 64) * sizeof(float);  // ~66 KB
    cudaFuncSetAttribute(flash_fwd, cudaFuncAttributeMaxDynamicSharedMemorySize, (int)shm);

    dim3 gemm_grid(E_ / 128, M_ / 128);  // (8, 32)
    sgemm_nt<<<gemm_grid, 256>>>(x, Wq, q, M_, E_, E_);
    sgemm_nt<<<gemm_grid, 256>>>(x, Wk, k, M_, E_, E_);
    sgemm_nt<<<gemm_grid, 256>>>(x, Wv, v, M_, E_, E_);

    dim3 attn_grid(S_ / 64, H_, B_);     // (32, 16, 2)
    flash_fwd<<<attn_grid, 256, shm>>>(q, k, v, c);

    sgemm_nt<<<gemm_grid, 256>>>(c, Wo, out, M_, E_, E_);
}

// round 2
// speedup vs baseline: 1.1045x; 1.1045x over previous
#include <cuda_runtime.h>
#include <math.h>

#define B_ 2
#define S_ 2048
#define E_ 1024
#define H_ 16
#define D_ 64
#define M_ (B_*S_)

#define NEGINF (-1e30f)

// Scratch (allocation-free rule: __device__ globals)
__device__ float g_Q[B_*S_*E_];
__device__ float g_K[B_*S_*E_];
__device__ float g_V[B_*S_*E_];
__device__ float g_C[B_*S_*E_];

// ---------------------------------------------------------------------------
// Common SGEMM body (NT): C[128x128 tile] = A[M,1024] * Bw[N,1024]^T
// 128x128 block tile, K-tile 16, 256 threads, 8x8 microtile,
// 2-stage smem double buffering (one __syncthreads per K-tile).
// ---------------------------------------------------------------------------
__device__ __forceinline__ void gemm_body(const float* __restrict__ A,
                                          const float* __restrict__ Bw,
                                          float* __restrict__ C,
                                          int bm, int bn)
{
    __shared__ float As[2][16][128];
    __shared__ float Bs[2][16][128];

    const int tid = threadIdx.x;
    const int tm = (tid >> 4) << 3;
    const int tn = (tid & 15) << 3;
    const int lrow = tid >> 2;          // 0..63 (also handles lrow+64)
    const int lkq  = (tid & 3) << 2;    // 0,4,8,12

    const float* Ap = A  + (size_t)(bm + lrow) * E_ + lkq;
    const float* Bp = Bw + (size_t)(bn + lrow) * E_ + lkq;

    float acc[8][8] = {};

    // stage 0 load
    {
        float4 a0 = *(const float4*)(Ap);
        float4 a1 = *(const float4*)(Ap + (size_t)64 * E_);
        float4 b0 = *(const float4*)(Bp);
        float4 b1 = *(const float4*)(Bp + (size_t)64 * E_);
        As[0][lkq+0][lrow] = a0.x; As[0][lkq+1][lrow] = a0.y;
        As[0][lkq+2][lrow] = a0.z; As[0][lkq+3][lrow] = a0.w;
        As[0][lkq+0][lrow+64] = a1.x; As[0][lkq+1][lrow+64] = a1.y;
        As[0][lkq+2][lrow+64] = a1.z; As[0][lkq+3][lrow+64] = a1.w;
        Bs[0][lkq+0][lrow] = b0.x; Bs[0][lkq+1][lrow] = b0.y;
        Bs[0][lkq+2][lrow] = b0.z; Bs[0][lkq+3][lrow] = b0.w;
        Bs[0][lkq+0][lrow+64] = b1.x; Bs[0][lkq+1][lrow+64] = b1.y;
        Bs[0][lkq+2][lrow+64] = b1.z; Bs[0][lkq+3][lrow+64] = b1.w;
    }
    __syncthreads();

    int buf = 0;
    for (int k0 = 0; k0 < E_; k0 += 16) {
        float4 na0, na1, nb0, nb1;
        const bool more = (k0 + 16) < E_;
        if (more) {
            na0 = *(const float4*)(Ap + k0 + 16);
            na1 = *(const float4*)(Ap + (size_t)64 * E_ + k0 + 16);
            nb0 = *(const float4*)(Bp + k0 + 16);
            nb1 = *(const float4*)(Bp + (size_t)64 * E_ + k0 + 16);
        }
        #pragma unroll
        for (int kk = 0; kk < 16; kk++) {
            float a[8], b[8];
            *(float4*)&a[0] = *(float4*)&As[buf][kk][tm];
            *(float4*)&a[4] = *(float4*)&As[buf][kk][tm + 4];
            *(float4*)&b[0] = *(float4*)&Bs[buf][kk][tn];
            *(float4*)&b[4] = *(float4*)&Bs[buf][kk][tn + 4];
            #pragma unroll
            for (int i = 0; i < 8; i++)
                #pragma unroll
                for (int j = 0; j < 8; j++)
                    acc[i][j] = fmaf(a[i], b[j], acc[i][j]);
        }
        if (more) {
            const int nb_ = buf ^ 1;
            As[nb_][lkq+0][lrow] = na0.x; As[nb_][lkq+1][lrow] = na0.y;
            As[nb_][lkq+2][lrow] = na0.z; As[nb_][lkq+3][lrow] = na0.w;
            As[nb_][lkq+0][lrow+64] = na1.x; As[nb_][lkq+1][lrow+64] = na1.y;
            As[nb_][lkq+2][lrow+64] = na1.z; As[nb_][lkq+3][lrow+64] = na1.w;
            Bs[nb_][lkq+0][lrow] = nb0.x; Bs[nb_][lkq+1][lrow] = nb0.y;
            Bs[nb_][lkq+2][lrow] = nb0.z; Bs[nb_][lkq+3][lrow] = nb0.w;
            Bs[nb_][lkq+0][lrow+64] = nb1.x; Bs[nb_][lkq+1][lrow+64] = nb1.y;
            Bs[nb_][lkq+2][lrow+64] = nb1.z; Bs[nb_][lkq+3][lrow+64] = nb1.w;
        }
        __syncthreads();
        buf ^= 1;
    }

    #pragma unroll
    for (int i = 0; i < 8; i++) {
        float* cp = C + (size_t)(bm + tm + i) * E_ + bn + tn;
        *(float4*)cp       = make_float4(acc[i][0], acc[i][1], acc[i][2], acc[i][3]);
        *(float4*)(cp + 4) = make_float4(acc[i][4], acc[i][5], acc[i][6], acc[i][7]);
    }
}

// Fused Q/K/V projection: one launch, 768 blocks
__global__ __launch_bounds__(256, 2)
void sgemm_qkv(const float* __restrict__ x, const float* __restrict__ Wq,
               const float* __restrict__ Wk, const float* __restrict__ Wv)
{
    const int sel = blockIdx.x >> 3;
    const float* Bw = (sel == 0) ? Wq : (sel == 1) ? Wk : Wv;
    float* C = (sel == 0) ? g_Q : (sel == 1) ? g_K : g_V;
    gemm_body(x, Bw, C, blockIdx.y * 128, (blockIdx.x & 7) * 128);
}

// Output projection
__global__ __launch_bounds__(256, 2)
void sgemm_o(const float* __restrict__ Wo, float* __restrict__ out)
{
    gemm_body(g_C, Wo, out, blockIdx.y * 128, blockIdx.x * 128);
}

// ---------------------------------------------------------------------------
// Flash attention v2, fp32, causal.
// BM=128 (Q rows) x BN=64 (K cols), 256 threads, 8x4 microtile (1.5 B/FMA).
// Q/K transposed in smem with XOR chunk swizzle (2-way STS conflicts).
// Softmax fully in registers via half-warp shuffles (row owned by 16 lanes).
// Ps stride 68 to avoid conflicts on the PV reads.
// ---------------------------------------------------------------------------
__device__ __forceinline__ float redmax16(float v) {
    v = fmaxf(v, __shfl_xor_sync(0xffffffffu, v, 1));
    v = fmaxf(v, __shfl_xor_sync(0xffffffffu, v, 2));
    v = fmaxf(v, __shfl_xor_sync(0xffffffffu, v, 4));
    v = fmaxf(v, __shfl_xor_sync(0xffffffffu, v, 8));
    return v;
}
__device__ __forceinline__ float redsum16(float v) {
    v += __shfl_xor_sync(0xffffffffu, v, 1);
    v += __shfl_xor_sync(0xffffffffu, v, 2);
    v += __shfl_xor_sync(0xffffffffu, v, 4);
    v += __shfl_xor_sync(0xffffffffu, v, 8);
    return v;
}

#define FLASH_SMEM ((64*128 + 64*64 + 64*64 + 128*68) * sizeof(float))

__global__ __launch_bounds__(256, 2)
void flash_fwd()
{
    extern __shared__ float sm[];
    float* Qs = sm;               // [64][128]  d-major, chunk-swizzled
    float* Ks = Qs + 64 * 128;    // [64][64]   d-major, chunk-swizzled
    float* Vs = Ks + 64 * 64;     // [64][64]   row-major
    float* Ps = Vs + 64 * 64;     // [128][68]  row-major, padded

    const int tid = threadIdx.x;
    const int qt = (S_ / 128 - 1) - (int)blockIdx.x;  // heavy tiles first
    const int h = blockIdx.y, b = blockIdx.z;
    const size_t base = (size_t)b * S_ * E_ + (size_t)h * D_;
    const float* Q  = g_Q + base;
    const float* Kp = g_K + base;
    const float* Vp = g_V + base;
    float* O = g_C + base;

    const int tx = tid & 15, ty = tid >> 4;
    const int r0 = ty << 3, c0 = tx << 2;
    const int lc  = tid & 15;   // d-chunk index for loads
    const int ln0 = tid >> 4;   // row base for loads

    // ---- Load Q tile transposed + swizzled (chunk ^= d>>2) ----
    #pragma unroll
    for (int l = 0; l < 8; l++) {
        const int mrow = ln0 + l * 16;
        float4 v = *(const float4*)(Q + (size_t)(qt * 128 + mrow) * E_ + lc * 4);
        const int pos = ((((mrow >> 2) ^ lc) << 2) + (mrow & 3));
        Qs[(4*lc + 0) * 128 + pos] = v.x;
        Qs[(4*lc + 1) * 128 + pos] = v.y;
        Qs[(4*lc + 2) * 128 + pos] = v.z;
        Qs[(4*lc + 3) * 128 + pos] = v.w;
    }

    float o[8][4] = {};
    float m[8], lsum[8];
    #pragma unroll
    for (int i = 0; i < 8; i++) { m[i] = NEGINF; lsum[i] = 0.0f; }

    const float scl = 8.0f;  // * sqrt(HEAD_DIM), faithful to reference
    const int nj = 2 * qt + 2;

    for (int jt = 0; jt < nj; jt++) {
        // ---- Load K (transposed+swizzled) and V (row-major) tiles ----
        #pragma unroll
        for (int l = 0; l < 4; l++) {
            const int n = ln0 + l * 16;
            float4 kv = *(const float4*)(Kp + (size_t)(jt * 64 + n) * E_ + lc * 4);
            const int pos = ((((n >> 2) ^ lc) << 2) + (n & 3));
            Ks[(4*lc + 0) * 64 + pos] = kv.x;
            Ks[(4*lc + 1) * 64 + pos] = kv.y;
            Ks[(4*lc + 2) * 64 + pos] = kv.z;
            Ks[(4*lc + 3) * 64 + pos] = kv.w;
            float4 vv = *(const float4*)(Vp + (size_t)(jt * 64 + n) * E_ + lc * 4);
            *(float4*)&Vs[n * 64 + lc * 4] = vv;
        }
        __syncthreads();

        // ---- S = Q K^T, 8x4 microtile ----
        float s[8][4] = {};
        for (int d0 = 0; d0 < 64; d0 += 4) {
            const int sw = d0 >> 2;
            const int qp0 = ((2 * ty) ^ sw) << 2;
            const int qp1 = ((2 * ty + 1) ^ sw) << 2;
            const int kpp = (tx ^ sw) << 2;
            #pragma unroll
            for (int t = 0; t < 4; t++) {
                const int d = d0 + t;
                float4 qa = *(float4*)&Qs[d * 128 + qp0];
                float4 qb = *(float4*)&Qs[d * 128 + qp1];
                float4 kf = *(float4*)&Ks[d * 64 + kpp];
                float qv[8] = {qa.x, qa.y, qa.z, qa.w, qb.x, qb.y, qb.z, qb.w};
                #pragma unroll
                for (int i = 0; i < 8; i++) {
                    s[i][0] = fmaf(qv[i], kf.x, s[i][0]);
                    s[i][1] = fmaf(qv[i], kf.y, s[i][1]);
                    s[i][2] = fmaf(qv[i], kf.z, s[i][2]);
                    s[i][3] = fmaf(qv[i], kf.w, s[i][3]);
                }
            }
        }

        // ---- scale + causal mask + register softmax (shfl over 16 lanes) ----
        const bool maskt = (jt >= 2 * qt);
        #pragma unroll
        for (int i = 0; i < 8; i++) {
            float s0 = s[i][0] * scl, s1 = s[i][1] * scl;
            float s2 = s[i][2] * scl, s3 = s[i][3] * scl;
            if (maskt) {
                const int qrow = qt * 128 + r0 + i;
                const int kc = jt * 64 + c0;
                s0 = (kc + 0 <= qrow) ? s0 : NEGINF;
                s1 = (kc + 1 <= qrow) ? s1 : NEGINF;
                s2 = (kc + 2 <= qrow) ? s2 : NEGINF;
                s3 = (kc + 3 <= qrow) ? s3 : NEGINF;
            }
            float mx = redmax16(fmaxf(fmaxf(s0, s1), fmaxf(s2, s3)));
            const float mnew = fmaxf(m[i], mx);
            const float alpha = __expf(m[i] - mnew);
            const float p0 = __expf(s0 - mnew);
            const float p1 = __expf(s1 - mnew);
            const float p2 = __expf(s2 - mnew);
            const float p3 = __expf(s3 - mnew);
            const float sum = redsum16((p0 + p1) + (p2 + p3));
            lsum[i] = lsum[i] * alpha + sum;
            m[i] = mnew;
            o[i][0] *= alpha; o[i][1] *= alpha; o[i][2] *= alpha; o[i][3] *= alpha;
            *(float4*)&Ps[(r0 + i) * 68 + c0] = make_float4(p0, p1, p2, p3);
        }
        __syncthreads();

        // ---- O += P V ----
        for (int k = 0; k < 64; k += 4) {
            float4 v0 = *(float4*)&Vs[(k + 0) * 64 + c0];
            float4 v1 = *(float4*)&Vs[(k + 1) * 64 + c0];
            float4 v2 = *(float4*)&Vs[(k + 2) * 64 + c0];
            float4 v3 = *(float4*)&Vs[(k + 3) * 64 + c0];
            #pragma unroll
            for (int i = 0; i < 8; i++) {
                float4 p = *(float4*)&Ps[(r0 + i) * 68 + k];
                o[i][0] = fmaf(p.x, v0.x, fmaf(p.y, v1.x, fmaf(p.z, v2.x, fmaf(p.w, v3.x, o[i][0]))));
                o[i][1] = fmaf(p.x, v0.y, fmaf(p.y, v1.y, fmaf(p.z, v2.y, fmaf(p.w, v3.y, o[i][1]))));
                o[i][2] = fmaf(p.x, v0.z, fmaf(p.y, v1.z, fmaf(p.z, v2.z, fmaf(p.w, v3.z, o[i][2]))));
                o[i][3] = fmaf(p.x, v0.w, fmaf(p.y, v1.w, fmaf(p.z, v2.w, fmaf(p.w, v3.w, o[i][3]))));
            }
        }
        __syncthreads();
    }

    // ---- normalize and write ----
    #pragma unroll
    for (int i = 0; i < 8; i++) {
        const float inv = 1.0f / lsum[i];
        *(float4*)&O[(size_t)(qt * 128 + r0 + i) * E_ + c0] =
            make_float4(o[i][0] * inv, o[i][1] * inv, o[i][2] * inv, o[i][3] * inv);
    }
}

// ---------------------------------------------------------------------------
extern "C" void kernel_launch(void* const* d_in, const int* in_sizes, int n_in,
                              void* d_out, int out_size)
{
    const float* x  = (const float*)d_in[0];
    const float* Wq = (const float*)d_in[1];
    const float* Wk = (const float*)d_in[2];
    const float* Wv = (const float*)d_in[3];
    const float* Wo = (const float*)d_in[4];
    float* out = (float*)d_out;

    cudaFuncSetAttribute(flash_fwd, cudaFuncAttributeMaxDynamicSharedMemorySize,
                         (int)FLASH_SMEM);

    dim3 gq(24, 32);
    sgemm_qkv<<<gq, 256>>>(x, Wq, Wk, Wv);

    dim3 ga(S_ / 128, H_, B_);   // (16, 16, 2)
    flash_fwd<<<ga, 256, FLASH_SMEM>>>();

    dim3 go(8, 32);
    sgemm_o<<<go, 256>>>(Wo, out);
}

// round 5
// speedup vs baseline: 1.3244x; 1.1990x over previous
#include <cuda_runtime.h>
#include <cstdint>
#include <math.h>

#define B_ 2
#define S_ 2048
#define E_ 1024
#define H_ 16
#define D_ 64
#define M_ (B_*S_)

#define NEGINF (-1e30f)

// Scratch (allocation-free rule: __device__ globals)
__device__ float g_Q[B_*S_*E_];
__device__ float g_K[B_*S_*E_];
__device__ float g_V[B_*S_*E_];
__device__ float g_C[B_*S_*E_];

// ===========================================================================
// mma.sync helpers (family-portable: sm_80+; NO tcgen05 — harness targets
// compute_100 virtual arch which forbids accelerated-family PTX)
// ===========================================================================
__device__ __forceinline__ uint32_t smem_u32(const void* p) {
    uint32_t a;
    asm("{ .reg .u64 t; cvta.to.shared.u64 t, %1; cvt.u32.u64 %0, t; }"
        : "=r"(a) : "l"(p));
    return a;
}
__device__ __forceinline__ float tf32_rnd(float a) {
    uint32_t u;
    asm("cvt.rna.tf32.f32 %0, %1;" : "=r"(u) : "f"(a));
    return __uint_as_float(u);
}
__device__ __forceinline__ void ldsm4(uint32_t& r0, uint32_t& r1,
                                      uint32_t& r2, uint32_t& r3, uint32_t addr) {
    asm volatile("ldmatrix.sync.aligned.m8n8.x4.shared.b16 {%0,%1,%2,%3}, [%4];"
                 : "=r"(r0), "=r"(r1), "=r"(r2), "=r"(r3) : "r"(addr));
}
__device__ __forceinline__ void mma_tf32(float* c, const uint32_t* a,
                                         uint32_t b0, uint32_t b1) {
    asm volatile("mma.sync.aligned.m16n8k8.row.col.f32.tf32.tf32.f32 "
                 "{%0,%1,%2,%3}, {%4,%5,%6,%7}, {%8,%9}, {%0,%1,%2,%3};"
                 : "+f"(c[0]), "+f"(c[1]), "+f"(c[2]), "+f"(c[3])
                 : "r"(a[0]), "r"(a[1]), "r"(a[2]), "r"(a[3]), "r"(b0), "r"(b1));
}

// ===========================================================================
// 3xTF32 mma.sync GEMM (NT): C[128x128] = A[M,1024] * Bw[N,1024]^T
// 8 warps, warp tile 64x32, K-tile 32. Smem: Ahi|Alo|Bhi|Blo k-major
// [128][32] tiles, SW128-swizzled. A=hi+lo split in registers at load;
// 3 MMA streams (hi*hi + hi*lo + lo*hi).
// ===========================================================================
#define TILE_B   16384                 // one 128x32 fp32 tile
#define GEMM_SMEM (4 * TILE_B + 128)

__device__ __forceinline__ void tc_gemm_body(const float* __restrict__ A,
                                             const float* __restrict__ Bw,
                                             float* __restrict__ C,
                                             int bm, int bn)
{
    extern __shared__ char smraw[];
    char* smb = (char*)(((uintptr_t)smraw + 127) & ~(uintptr_t)127);
    const uint32_t sAhi = smem_u32(smb);
    const uint32_t sAlo = sAhi + TILE_B;
    const uint32_t sBhi = sAhi + 2 * TILE_B;
    const uint32_t sBlo = sAhi + 3 * TILE_B;

    const int tid  = threadIdx.x;
    const int wid  = tid >> 5;
    const int lane = tid & 31;
    const int wm = (wid >> 2) * 64;       // 0 or 64
    const int wn = (wid & 3) * 32;        // 0..96

    // ldmatrix lane roles
    const int rlbA   = (lane & 7) + ((lane >> 3) & 1) * 8;
    const int col16A = (lane >> 4) & 1;
    const int rlbB   = (lane & 7) + ((lane >> 4) & 1) * 8;
    const int col16B = (lane >> 3) & 1;

    // Precompute per-fragment row addresses + swizzle terms
    uint32_t aRow[4], aXor[4], bRow[2], bXor[2];
    #pragma unroll
    for (int f = 0; f < 4; f++) {
        const int r = wm + f * 16 + rlbA;
        aRow[f] = r * 128;
        aXor[f] = ((r & 7) << 4) ^ (col16A * 16);
    }
    #pragma unroll
    for (int p = 0; p < 2; p++) {
        const int r = wn + p * 16 + rlbB;
        bRow[p] = r * 128;
        bXor[p] = ((r & 7) << 4) ^ (col16B * 16);
    }

    // LDG indexing for tile fill: 1024 float4s, 256 threads x 4
    const int frow = tid >> 1;               // 0..127 (2 float4/row/thread? no:)
    // Use idx-based: idx = tid + l*256; row = idx>>3; c4 = idx&7
    const float* Abase = A  + (size_t)bm * E_;
    const float* Bbase = Bw + (size_t)bn * E_;
    (void)frow;

    float acc[4][4][4] = {};
    float4 rgA[4], rgB[4];

    // preload k-tile 0
    #pragma unroll
    for (int l = 0; l < 4; l++) {
        const int idx = tid + l * 256;
        const int row = idx >> 3, c4 = idx & 7;
        rgA[l] = *(const float4*)(Abase + (size_t)row * E_ + c4 * 4);
        rgB[l] = *(const float4*)(Bbase + (size_t)row * E_ + c4 * 4);
    }

    for (int kt = 0; kt < 32; kt++) {
        // STS with split (hi = tf32 round, lo = tf32(residual))
        #pragma unroll
        for (int l = 0; l < 4; l++) {
            const int idx = tid + l * 256;
            const int row = idx >> 3, c4 = idx & 7;
            const int off = row * 128 + (((c4 * 16) ^ ((row & 7) << 4)));
            float4 a = rgA[l];
            float hx = tf32_rnd(a.x), hy = tf32_rnd(a.y),
                  hz = tf32_rnd(a.z), hw = tf32_rnd(a.w);
            *(float4*)(smb + off) = make_float4(hx, hy, hz, hw);
            *(float4*)(smb + TILE_B + off) =
                make_float4(tf32_rnd(a.x - hx), tf32_rnd(a.y - hy),
                            tf32_rnd(a.z - hz), tf32_rnd(a.w - hw));
            float4 b = rgB[l];
            float gx = tf32_rnd(b.x), gy = tf32_rnd(b.y),
                  gz = tf32_rnd(b.z), gw = tf32_rnd(b.w);
            *(float4*)(smb + 2 * TILE_B + off) = make_float4(gx, gy, gz, gw);
            *(float4*)(smb + 3 * TILE_B + off) =
                make_float4(tf32_rnd(b.x - gx), tf32_rnd(b.y - gy),
                            tf32_rnd(b.z - gz), tf32_rnd(b.w - gw));
        }
        __syncthreads();

        // prefetch next k-tile
        if (kt + 1 < 32) {
            const int k0 = (kt + 1) * 32;
            #pragma unroll
            for (int l = 0; l < 4; l++) {
                const int idx = tid + l * 256;
                const int row = idx >> 3, c4 = idx & 7;
                rgA[l] = *(const float4*)(Abase + (size_t)row * E_ + k0 + c4 * 4);
                rgB[l] = *(const float4*)(Bbase + (size_t)row * E_ + k0 + c4 * 4);
            }
        }

        // compute 4 k8 slices
        #pragma unroll
        for (int s = 0; s < 4; s++) {
            const uint32_t colb = s * 32;
            uint32_t ah[4][4], al[4][4], bh[2][4], bl[2][4];
            #pragma unroll
            for (int f = 0; f < 4; f++) {
                const uint32_t ad = aRow[f] + (colb ^ aXor[f]);
                ldsm4(ah[f][0], ah[f][1], ah[f][2], ah[f][3], sAhi + ad);
                ldsm4(al[f][0], al[f][1], al[f][2], al[f][3], sAlo + ad);
            }
            #pragma unroll
            for (int p = 0; p < 2; p++) {
                const uint32_t bd = bRow[p] + (colb ^ bXor[p]);
                ldsm4(bh[p][0], bh[p][1], bh[p][2], bh[p][3], sBhi + bd);
                ldsm4(bl[p][0], bl[p][1], bl[p][2], bl[p][3], sBlo + bd);
            }
            // stream 1: hi*hi
            #pragma unroll
            for (int f = 0; f < 4; f++)
                #pragma unroll
                for (int g = 0; g < 4; g++)
                    mma_tf32(acc[f][g], ah[f], bh[g >> 1][(g & 1) * 2],
                                               bh[g >> 1][(g & 1) * 2 + 1]);
            // stream 2: hi*lo
            #pragma unroll
            for (int f = 0; f < 4; f++)
                #pragma unroll
                for (int g = 0; g < 4; g++)
                    mma_tf32(acc[f][g], ah[f], bl[g >> 1][(g & 1) * 2],
                                               bl[g >> 1][(g & 1) * 2 + 1]);
            // stream 3: lo*hi
            #pragma unroll
            for (int f = 0; f < 4; f++)
                #pragma unroll
                for (int g = 0; g < 4; g++)
                    mma_tf32(acc[f][g], al[f], bh[g >> 1][(g & 1) * 2],
                                               bh[g >> 1][(g & 1) * 2 + 1]);
        }
        __syncthreads();
    }

    // epilogue: per-frag writes (float2)
    #pragma unroll
    for (int f = 0; f < 4; f++) {
        const int r0 = bm + wm + f * 16 + (lane >> 2);
        #pragma unroll
        for (int g = 0; g < 4; g++) {
            const int cc = bn + wn + g * 8 + (lane & 3) * 2;
            *(float2*)(C + (size_t)r0 * E_ + cc) =
                make_float2(acc[f][g][0], acc[f][g][1]);
            *(float2*)(C + (size_t)(r0 + 8) * E_ + cc) =
                make_float2(acc[f][g][2], acc[f][g][3]);
        }
    }
}

__global__ __launch_bounds__(256)
void tc_gemm_qkv(const float* __restrict__ x, const float* __restrict__ Wq,
                 const float* __restrict__ Wk, const float* __restrict__ Wv)
{
    const int sel = blockIdx.x >> 3;
    const float* Bw = (sel == 0) ? Wq : (sel == 1) ? Wk : Wv;
    float* C = (sel == 0) ? g_Q : (sel == 1) ? g_K : g_V;
    tc_gemm_body(x, Bw, C, blockIdx.y * 128, (blockIdx.x & 7) * 128);
}

__global__ __launch_bounds__(256)
void tc_gemm_o(const float* __restrict__ Wo, float* __restrict__ out)
{
    tc_gemm_body(g_C, Wo, out, blockIdx.y * 128, blockIdx.x * 128);
}

// ===========================================================================
// Flash attention v2, fp32, causal (unchanged — passed at 7.7e-6).
// ===========================================================================
__device__ __forceinline__ float redmax16(float v) {
    v = fmaxf(v, __shfl_xor_sync(0xffffffffu, v, 1));
    v = fmaxf(v, __shfl_xor_sync(0xffffffffu, v, 2));
    v = fmaxf(v, __shfl_xor_sync(0xffffffffu, v, 4));
    v = fmaxf(v, __shfl_xor_sync(0xffffffffu, v, 8));
    return v;
}
__device__ __forceinline__ float redsum16(float v) {
    v += __shfl_xor_sync(0xffffffffu, v, 1);
    v += __shfl_xor_sync(0xffffffffu, v, 2);
    v += __shfl_xor_sync(0xffffffffu, v, 4);
    v += __shfl_xor_sync(0xffffffffu, v, 8);
    return v;
}

#define FLASH_SMEM ((64*128 + 64*64 + 64*64 + 128*68) * sizeof(float))

__global__ __launch_bounds__(256, 2)
void flash_fwd()
{
    extern __shared__ float smf[];
    float* Qs = smf;              // [64][128]  d-major, chunk-swizzled
    float* Ks = Qs + 64 * 128;    // [64][64]   d-major, chunk-swizzled
    float* Vs = Ks + 64 * 64;     // [64][64]   row-major
    float* Ps = Vs + 64 * 64;     // [128][68]  row-major, padded

    const int tid = threadIdx.x;
    const int qt = (S_ / 128 - 1) - (int)blockIdx.x;  // heavy tiles first
    const int h = blockIdx.y, b = blockIdx.z;
    const size_t base = (size_t)b * S_ * E_ + (size_t)h * D_;
    const float* Q  = g_Q + base;
    const float* Kp = g_K + base;
    const float* Vp = g_V + base;
    float* O = g_C + base;

    const int tx = tid & 15, ty = tid >> 4;
    const int r0 = ty << 3, c0 = tx << 2;
    const int lc  = tid & 15;
    const int ln0 = tid >> 4;

    #pragma unroll
    for (int l = 0; l < 8; l++) {
        const int mrow = ln0 + l * 16;
        float4 v = *(const float4*)(Q + (size_t)(qt * 128 + mrow) * E_ + lc * 4);
        const int pos = ((((mrow >> 2) ^ lc) << 2) + (mrow & 3));
        Qs[(4*lc + 0) * 128 + pos] = v.x;
        Qs[(4*lc + 1) * 128 + pos] = v.y;
        Qs[(4*lc + 2) * 128 + pos] = v.z;
        Qs[(4*lc + 3) * 128 + pos] = v.w;
    }

    float o[8][4] = {};
    float m[8], lsum[8];
    #pragma unroll
    for (int i = 0; i < 8; i++) { m[i] = NEGINF; lsum[i] = 0.0f; }

    const float scl = 8.0f;
    const int nj = 2 * qt + 2;

    for (int jt = 0; jt < nj; jt++) {
        #pragma unroll
        for (int l = 0; l < 4; l++) {
            const int n = ln0 + l * 16;
            float4 kv = *(const float4*)(Kp + (size_t)(jt * 64 + n) * E_ + lc * 4);
            const int pos = ((((n >> 2) ^ lc) << 2) + (n & 3));
            Ks[(4*lc + 0) * 64 + pos] = kv.x;
            Ks[(4*lc + 1) * 64 + pos] = kv.y;
            Ks[(4*lc + 2) * 64 + pos] = kv.z;
            Ks[(4*lc + 3) * 64 + pos] = kv.w;
            float4 vv = *(const float4*)(Vp + (size_t)(jt * 64 + n) * E_ + lc * 4);
            *(float4*)&Vs[n * 64 + lc * 4] = vv;
        }
        __syncthreads();

        float s[8][4] = {};
        for (int d0 = 0; d0 < 64; d0 += 4) {
            const int sw = d0 >> 2;
            const int qp0 = ((2 * ty) ^ sw) << 2;
            const int qp1 = ((2 * ty + 1) ^ sw) << 2;
            const int kpp = (tx ^ sw) << 2;
            #pragma unroll
            for (int t = 0; t < 4; t++) {
                const int d = d0 + t;
                float4 qa = *(float4*)&Qs[d * 128 + qp0];
                float4 qb = *(float4*)&Qs[d * 128 + qp1];
                float4 kf = *(float4*)&Ks[d * 64 + kpp];
                float qv[8] = {qa.x, qa.y, qa.z, qa.w, qb.x, qb.y, qb.z, qb.w};
                #pragma unroll
                for (int i = 0; i < 8; i++) {
                    s[i][0] = fmaf(qv[i], kf.x, s[i][0]);
                    s[i][1] = fmaf(qv[i], kf.y, s[i][1]);
                    s[i][2] = fmaf(qv[i], kf.z, s[i][2]);
                    s[i][3] = fmaf(qv[i], kf.w, s[i][3]);
                }
            }
        }

        const bool maskt = (jt >= 2 * qt);
        #pragma unroll
        for (int i = 0; i < 8; i++) {
            float s0 = s[i][0] * scl, s1 = s[i][1] * scl;
            float s2 = s[i][2] * scl, s3 = s[i][3] * scl;
            if (maskt) {
                const int qrow = qt * 128 + r0 + i;
                const int kc = jt * 64 + c0;
                s0 = (kc + 0 <= qrow) ? s0 : NEGINF;
                s1 = (kc + 1 <= qrow) ? s1 : NEGINF;
                s2 = (kc + 2 <= qrow) ? s2 : NEGINF;
                s3 = (kc + 3 <= qrow) ? s3 : NEGINF;
            }
            float mx = redmax16(fmaxf(fmaxf(s0, s1), fmaxf(s2, s3)));
            const float mnew = fmaxf(m[i], mx);
            const float alpha = __expf(m[i] - mnew);
            const float p0 = __expf(s0 - mnew);
            const float p1 = __expf(s1 - mnew);
            const float p2 = __expf(s2 - mnew);
            const float p3 = __expf(s3 - mnew);
            const float sum = redsum16((p0 + p1) + (p2 + p3));
            lsum[i] = lsum[i] * alpha + sum;
            m[i] = mnew;
            o[i][0] *= alpha; o[i][1] *= alpha; o[i][2] *= alpha; o[i][3] *= alpha;
            *(float4*)&Ps[(r0 + i) * 68 + c0] = make_float4(p0, p1, p2, p3);
        }
        __syncthreads();

        for (int k = 0; k < 64; k += 4) {
            float4 v0 = *(float4*)&Vs[(k + 0) * 64 + c0];
            float4 v1 = *(float4*)&Vs[(k + 1) * 64 + c0];
            float4 v2 = *(float4*)&Vs[(k + 2) * 64 + c0];
            float4 v3 = *(float4*)&Vs[(k + 3) * 64 + c0];
            #pragma unroll
            for (int i = 0; i < 8; i++) {
                float4 p = *(float4*)&Ps[(r0 + i) * 68 + k];
                o[i][0] = fmaf(p.x, v0.x, fmaf(p.y, v1.x, fmaf(p.z, v2.x, fmaf(p.w, v3.x, o[i][0]))));
                o[i][1] = fmaf(p.x, v0.y, fmaf(p.y, v1.y, fmaf(p.z, v2.y, fmaf(p.w, v3.y, o[i][1]))));
                o[i][2] = fmaf(p.x, v0.z, fmaf(p.y, v1.z, fmaf(p.z, v2.z, fmaf(p.w, v3.z, o[i][2]))));
                o[i][3] = fmaf(p.x, v0.w, fmaf(p.y, v1.w, fmaf(p.z, v2.w, fmaf(p.w, v3.w, o[i][3]))));
            }
        }
        __syncthreads();
    }

    #pragma unroll
    for (int i = 0; i < 8; i++) {
        const float inv = 1.0f / lsum[i];
        *(float4*)&O[(size_t)(qt * 128 + r0 + i) * E_ + c0] =
            make_float4(o[i][0] * inv, o[i][1] * inv, o[i][2] * inv, o[i][3] * inv);
    }
}

// ===========================================================================
extern "C" void kernel_launch(void* const* d_in, const int* in_sizes, int n_in,
                              void* d_out, int out_size)
{
    const float* x  = (const float*)d_in[0];
    const float* Wq = (const float*)d_in[1];
    const float* Wk = (const float*)d_in[2];
    const float* Wv = (const float*)d_in[3];
    const float* Wo = (const float*)d_in[4];
    float* out = (float*)d_out;

    cudaFuncSetAttribute(tc_gemm_qkv, cudaFuncAttributeMaxDynamicSharedMemorySize, GEMM_SMEM);
    cudaFuncSetAttribute(tc_gemm_o,   cudaFuncAttributeMaxDynamicSharedMemorySize, GEMM_SMEM);
    cudaFuncSetAttribute(flash_fwd,   cudaFuncAttributeMaxDynamicSharedMemorySize, (int)FLASH_SMEM);

    dim3 gq(24, 32);
    tc_gemm_qkv<<<gq, 256, GEMM_SMEM>>>(x, Wq, Wk, Wv);

    dim3 ga(S_ / 128, H_, B_);
    flash_fwd<<<ga, 256, FLASH_SMEM>>>();

    dim3 go(8, 32);
    tc_gemm_o<<<go, 256, GEMM_SMEM>>>(Wo, out);
}

// round 6
// speedup vs baseline: 1.3879x; 1.0479x over previous
#include <cuda_runtime.h>
#include <cstdint>
#include <math.h>

#define B_ 2
#define S_ 2048
#define E_ 1024
#define H_ 16
#define D_ 64
#define M_ (B_*S_)

#define NEGINF (-1e30f)

// Scratch (allocation-free rule: __device__ globals)
__device__ float g_Q[B_*S_*E_];
__device__ float g_K[B_*S_*E_];
__device__ float g_V[B_*S_*E_];
__device__ float g_Vt[B_*H_*D_*S_];   // V transposed: [(b*H+h)][d][s]
__device__ float g_C[B_*S_*E_];

// ===========================================================================
// mma.sync helpers (family-portable sm_80+; tcgen05 unavailable: harness
// compiles virtual arch compute_100 which forbids accelerated-family PTX)
// ===========================================================================
__device__ __forceinline__ uint32_t smem_u32(const void* p) {
    uint32_t a;
    asm("{ .reg .u64 t; cvta.to.shared.u64 t, %1; cvt.u32.u64 %0, t; }"
        : "=r"(a) : "l"(p));
    return a;
}
__device__ __forceinline__ float tf32_rnd(float a) {
    uint32_t u;
    asm("cvt.rna.tf32.f32 %0, %1;" : "=r"(u) : "f"(a));
    return __uint_as_float(u);
}
__device__ __forceinline__ void ldsm4(uint32_t& r0, uint32_t& r1,
                                      uint32_t& r2, uint32_t& r3, uint32_t addr) {
    asm volatile("ldmatrix.sync.aligned.m8n8.x4.shared.b16 {%0,%1,%2,%3}, [%4];"
                 : "=r"(r0), "=r"(r1), "=r"(r2), "=r"(r3) : "r"(addr));
}
__device__ __forceinline__ void mma_tf32(float* c, const uint32_t* a,
                                         uint32_t b0, uint32_t b1) {
    asm volatile("mma.sync.aligned.m16n8k8.row.col.f32.tf32.tf32.f32 "
                 "{%0,%1,%2,%3}, {%4,%5,%6,%7}, {%8,%9}, {%0,%1,%2,%3};"
                 : "+f"(c[0]), "+f"(c[1]), "+f"(c[2]), "+f"(c[3])
                 : "r"(a[0]), "r"(a[1]), "r"(a[2]), "r"(a[3]), "r"(b0), "r"(b1));
}

// ===========================================================================
// 3xTF32 mma.sync GEMM (NT): C[128x128] = A[M,1024] * Bw[N,1024]^T
// (unchanged from round 5 — passed, tensor=59%)
// ===========================================================================
#define TILE_B   16384
#define GEMM_SMEM (4 * TILE_B + 128)

__device__ __forceinline__ void tc_gemm_body(const float* __restrict__ A,
                                             const float* __restrict__ Bw,
                                             float* __restrict__ C,
                                             int bm, int bn)
{
    extern __shared__ char smraw[];
    char* smb = (char*)(((uintptr_t)smraw + 127) & ~(uintptr_t)127);
    const uint32_t sAhi = smem_u32(smb);
    const uint32_t sAlo = sAhi + TILE_B;
    const uint32_t sBhi = sAhi + 2 * TILE_B;
    const uint32_t sBlo = sAhi + 3 * TILE_B;

    const int tid  = threadIdx.x;
    const int wid  = tid >> 5;
    const int lane = tid & 31;
    const int wm = (wid >> 2) * 64;
    const int wn = (wid & 3) * 32;

    const int rlbA   = (lane & 7) + ((lane >> 3) & 1) * 8;
    const int col16A = (lane >> 4) & 1;
    const int rlbB   = (lane & 7) + ((lane >> 4) & 1) * 8;
    const int col16B = (lane >> 3) & 1;

    uint32_t aRow[4], aXor[4], bRow[2], bXor[2];
    #pragma unroll
    for (int f = 0; f < 4; f++) {
        const int r = wm + f * 16 + rlbA;
        aRow[f] = r * 128;
        aXor[f] = ((r & 7) << 4) ^ (col16A * 16);
    }
    #pragma unroll
    for (int p = 0; p < 2; p++) {
        const int r = wn + p * 16 + rlbB;
        bRow[p] = r * 128;
        bXor[p] = ((r & 7) << 4) ^ (col16B * 16);
    }

    const float* Abase = A  + (size_t)bm * E_;
    const float* Bbase = Bw + (size_t)bn * E_;

    float acc[4][4][4] = {};
    float4 rgA[4], rgB[4];

    #pragma unroll
    for (int l = 0; l < 4; l++) {
        const int idx = tid + l * 256;
        const int row = idx >> 3, c4 = idx & 7;
        rgA[l] = *(const float4*)(Abase + (size_t)row * E_ + c4 * 4);
        rgB[l] = *(const float4*)(Bbase + (size_t)row * E_ + c4 * 4);
    }

    for (int kt = 0; kt < 32; kt++) {
        #pragma unroll
        for (int l = 0; l < 4; l++) {
            const int idx = tid + l * 256;
            const int row = idx >> 3, c4 = idx & 7;
            const int off = row * 128 + (((c4 * 16) ^ ((row & 7) << 4)));
            float4 a = rgA[l];
            float hx = tf32_rnd(a.x), hy = tf32_rnd(a.y),
                  hz = tf32_rnd(a.z), hw = tf32_rnd(a.w);
            *(float4*)(smb + off) = make_float4(hx, hy, hz, hw);
            *(float4*)(smb + TILE_B + off) =
                make_float4(tf32_rnd(a.x - hx), tf32_rnd(a.y - hy),
                            tf32_rnd(a.z - hz), tf32_rnd(a.w - hw));
            float4 b = rgB[l];
            float gx = tf32_rnd(b.x), gy = tf32_rnd(b.y),
                  gz = tf32_rnd(b.z), gw = tf32_rnd(b.w);
            *(float4*)(smb + 2 * TILE_B + off) = make_float4(gx, gy, gz, gw);
            *(float4*)(smb + 3 * TILE_B + off) =
                make_float4(tf32_rnd(b.x - gx), tf32_rnd(b.y - gy),
                            tf32_rnd(b.z - gz), tf32_rnd(b.w - gw));
        }
        __syncthreads();

        if (kt + 1 < 32) {
            const int k0 = (kt + 1) * 32;
            #pragma unroll
            for (int l = 0; l < 4; l++) {
                const int idx = tid + l * 256;
                const int row = idx >> 3, c4 = idx & 7;
                rgA[l] = *(const float4*)(Abase + (size_t)row * E_ + k0 + c4 * 4);
                rgB[l] = *(const float4*)(Bbase + (size_t)row * E_ + k0 + c4 * 4);
            }
        }

        #pragma unroll
        for (int s = 0; s < 4; s++) {
            const uint32_t colb = s * 32;
            uint32_t ah[4][4], al[4][4], bh[2][4], bl[2][4];
            #pragma unroll
            for (int f = 0; f < 4; f++) {
                const uint32_t ad = aRow[f] + (colb ^ aXor[f]);
                ldsm4(ah[f][0], ah[f][1], ah[f][2], ah[f][3], sAhi + ad);
                ldsm4(al[f][0], al[f][1], al[f][2], al[f][3], sAlo + ad);
            }
            #pragma unroll
            for (int p = 0; p < 2; p++) {
                const uint32_t bd = bRow[p] + (colb ^ bXor[p]);
                ldsm4(bh[p][0], bh[p][1], bh[p][2], bh[p][3], sBhi + bd);
                ldsm4(bl[p][0], bl[p][1], bl[p][2], bl[p][3], sBlo + bd);
            }
            #pragma unroll
            for (int f = 0; f < 4; f++)
                #pragma unroll
                for (int g = 0; g < 4; g++)
                    mma_tf32(acc[f][g], ah[f], bh[g >> 1][(g & 1) * 2],
                                               bh[g >> 1][(g & 1) * 2 + 1]);
            #pragma unroll
            for (int f = 0; f < 4; f++)
                #pragma unroll
                for (int g = 0; g < 4; g++)
                    mma_tf32(acc[f][g], ah[f], bl[g >> 1][(g & 1) * 2],
                                               bl[g >> 1][(g & 1) * 2 + 1]);
            #pragma unroll
            for (int f = 0; f < 4; f++)
                #pragma unroll
                for (int g = 0; g < 4; g++)
                    mma_tf32(acc[f][g], al[f], bh[g >> 1][(g & 1) * 2],
                                               bh[g >> 1][(g & 1) * 2 + 1]);
        }
        __syncthreads();
    }

    #pragma unroll
    for (int f = 0; f < 4; f++) {
        const int r0 = bm + wm + f * 16 + (lane >> 2);
        #pragma unroll
        for (int g = 0; g < 4; g++) {
            const int cc = bn + wn + g * 8 + (lane & 3) * 2;
            *(float2*)(C + (size_t)r0 * E_ + cc) =
                make_float2(acc[f][g][0], acc[f][g][1]);
            *(float2*)(C + (size_t)(r0 + 8) * E_ + cc) =
                make_float2(acc[f][g][2], acc[f][g][3]);
        }
    }
}

__global__ __launch_bounds__(256)
void tc_gemm_qkv(const float* __restrict__ x, const float* __restrict__ Wq,
                 const float* __restrict__ Wk, const float* __restrict__ Wv)
{
    const int sel = blockIdx.x >> 3;
    const float* Bw = (sel == 0) ? Wq : (sel == 1) ? Wk : Wv;
    float* C = (sel == 0) ? g_Q : (sel == 1) ? g_K : g_V;
    tc_gemm_body(x, Bw, C, blockIdx.y * 128, (blockIdx.x & 7) * 128);
}

__global__ __launch_bounds__(256)
void tc_gemm_o(const float* __restrict__ Wo, float* __restrict__ out)
{
    tc_gemm_body(g_C, Wo, out, blockIdx.y * 128, blockIdx.x * 128);
}

// ===========================================================================
// V transpose: g_V [b][s][h*64+d]  ->  g_Vt [(b*H+h)][d][s]
// 64x64 tiles through padded smem; fully coalesced gmem on both sides.
// ===========================================================================
__global__ __launch_bounds__(256)
void v_transpose()
{
    __shared__ float ts[64 * 65];
    const int st = blockIdx.x;          // s-tile (0..31)
    const int h = blockIdx.y, b = blockIdx.z;
    const float* Vg = g_V + (size_t)b * S_ * E_ + h * D_;
    float* Vt = g_Vt + (size_t)(b * H_ + h) * D_ * S_;
    const int tid = threadIdx.x;

    #pragma unroll
    for (int l = 0; l < 4; l++) {
        const int idx = tid + l * 256;
        const int s = idx >> 4, c4 = idx & 15;
        float4 v = *(const float4*)(Vg + (size_t)(st * 64 + s) * E_ + c4 * 4);
        ts[(c4 * 4 + 0) * 65 + s] = v.x;
        ts[(c4 * 4 + 1) * 65 + s] = v.y;
        ts[(c4 * 4 + 2) * 65 + s] = v.z;
        ts[(c4 * 4 + 3) * 65 + s] = v.w;
    }
    __syncthreads();
    #pragma unroll
    for (int l = 0; l < 4; l++) {
        const int idx = tid + l * 256;
        const int d = idx >> 4, c4 = idx & 15;
        float4 w = make_float4(ts[d * 65 + c4 * 4 + 0], ts[d * 65 + c4 * 4 + 1],
                               ts[d * 65 + c4 * 4 + 2], ts[d * 65 + c4 * 4 + 3]);
        *(float4*)(Vt + (size_t)d * S_ + st * 64 + c4 * 4) = w;
    }
}

// ===========================================================================
// Flash attention on mma.sync 3xTF32.
// BM=128 (Q rows) x BN=64 (KV), 8 warps, warp = 16 Q rows.
// Q in registers (hi/lo frags); K, V^T hi/lo in smem; P hi/lo via warp-
// private smem. Softmax in registers on the mma accumulator layout.
// ===========================================================================
#define FSM_KHI 0
#define FSM_KLO 16384
#define FSM_VHI 32768
#define FSM_VLO 49152
#define FSM_PHI 65536
#define FSM_PLO 98304
#define FSM_TOTAL (131072 + 128)

__global__ __launch_bounds__(256)
void flash_mma()
{
    extern __shared__ char fraw[];
    char* fsm = (char*)(((uintptr_t)fraw + 127) & ~(uintptr_t)127);
    const uint32_t sb = smem_u32(fsm);

    const int tid = threadIdx.x, wid = tid >> 5, lane = tid & 31;
    const int qt = (S_ / 128 - 1) - (int)blockIdx.x;   // heavy tiles first
    const int h = blockIdx.y, b = blockIdx.z;

    const float* Qg  = g_Q + (size_t)b * S_ * E_ + h * D_;
    const float* Kg  = g_K + (size_t)b * S_ * E_ + h * D_;
    const float* Vtg = g_Vt + (size_t)(b * H_ + h) * D_ * S_;
    float* Og = g_C + (size_t)b * S_ * E_ + h * D_;

    // fragment lane constants (identical pattern to the validated GEMM)
    const int rlbA = (lane & 7) + ((lane >> 3) & 1) * 8;
    const int c16A = (lane >> 4) & 1;
    const int rlbB = (lane & 7) + ((lane >> 4) & 1) * 8;
    const int c16B = (lane >> 3) & 1;
    const uint32_t aX = ((rlbA & 7) << 4) ^ (c16A * 16);
    const uint32_t bX = ((rlbB & 7) << 4) ^ (c16B * 16);
    const int wq = wid * 16;
    const uint32_t rA = wq + rlbA;          // A-frag row (Q and P)
    uint32_t bR[4];
    #pragma unroll
    for (int p = 0; p < 4; p++) bR[p] = (p * 16 + rlbB) * 128;

    // ---- stage Q tile into P region (hi/lo split), extract register frags
    #pragma unroll
    for (int l = 0; l < 8; l++) {
        const int idx = tid + l * 256;
        const int row = idx >> 4, c4 = idx & 15;
        float4 q = *(const float4*)(Qg + (size_t)(qt * 128 + row) * E_ + c4 * 4);
        const int off = (c4 >> 3) * 16384 + row * 128 +
                        (((c4 & 7) * 16) ^ ((row & 7) << 4));
        float hx = tf32_rnd(q.x), hy = tf32_rnd(q.y),
              hz = tf32_rnd(q.z), hw = tf32_rnd(q.w);
        *(float4*)(fsm + FSM_PHI + off) = make_float4(hx, hy, hz, hw);
        *(float4*)(fsm + FSM_PLO + off) =
            make_float4(tf32_rnd(q.x - hx), tf32_rnd(q.y - hy),
                        tf32_rnd(q.z - hz), tf32_rnd(q.w - hw));
    }
    __syncthreads();
    uint32_t qh[8][4], ql[8][4];
    #pragma unroll
    for (int s = 0; s < 8; s++) {
        const uint32_t ad = (s >> 2) * 16384 + rA * 128 + (((s & 3) * 32) ^ aX);
        ldsm4(qh[s][0], qh[s][1], qh[s][2], qh[s][3], sb + FSM_PHI + ad);
        ldsm4(ql[s][0], ql[s][1], ql[s][2], ql[s][3], sb + FSM_PLO + ad);
    }
    __syncthreads();

    float o[8][4] = {};
    float mrow[2] = {NEGINF, NEGINF};
    float lrow[2] = {0.0f, 0.0f};

    const int nj = 2 * qt + 2;
    for (int jt = 0; jt < nj; jt++) {
        // ---- load K tile and V^T tile (hi/lo split) ----
        #pragma unroll
        for (int l = 0; l < 4; l++) {
            const int idx = tid + l * 256;
            const int row = idx >> 4, c4 = idx & 15;
            const int off = (c4 >> 3) * 8192 + row * 128 +
                            (((c4 & 7) * 16) ^ ((row & 7) << 4));
            float4 kv = *(const float4*)(Kg + (size_t)(jt * 64 + row) * E_ + c4 * 4);
            float hx = tf32_rnd(kv.x), hy = tf32_rnd(kv.y),
                  hz = tf32_rnd(kv.z), hw = tf32_rnd(kv.w);
            *(float4*)(fsm + FSM_KHI + off) = make_float4(hx, hy, hz, hw);
            *(float4*)(fsm + FSM_KLO + off) =
                make_float4(tf32_rnd(kv.x - hx), tf32_rnd(kv.y - hy),
                            tf32_rnd(kv.z - hz), tf32_rnd(kv.w - hw));
            float4 vv = *(const float4*)(Vtg + (size_t)row * S_ + jt * 64 + c4 * 4);
            float gx = tf32_rnd(vv.x), gy = tf32_rnd(vv.y),
                  gz = tf32_rnd(vv.z), gw = tf32_rnd(vv.w);
            *(float4*)(fsm + FSM_VHI + off) = make_float4(gx, gy, gz, gw);
            *(float4*)(fsm + FSM_VLO + off) =
                make_float4(tf32_rnd(vv.x - gx), tf32_rnd(vv.y - gy),
                            tf32_rnd(vv.z - gz), tf32_rnd(vv.w - gw));
        }
        __syncthreads();

        // ---- S = Q K^T (3 streams) ----
        float sc[8][4] = {};
        #pragma unroll
        for (int s = 0; s < 8; s++) {
            const uint32_t cof = (s >> 2) * 8192;
            const uint32_t colb = (s & 3) * 32;
            uint32_t kh[4][4], kl[4][4];
            #pragma unroll
            for (int p = 0; p < 4; p++) {
                const uint32_t ad = cof + bR[p] + (colb ^ bX);
                ldsm4(kh[p][0], kh[p][1], kh[p][2], kh[p][3], sb + FSM_KHI + ad);
                ldsm4(kl[p][0], kl[p][1], kl[p][2], kl[p][3], sb + FSM_KLO + ad);
            }
            #pragma unroll
            for (int nt = 0; nt < 8; nt++) {
                const uint32_t b0h = kh[nt >> 1][(nt & 1) * 2];
                const uint32_t b1h = kh[nt >> 1][(nt & 1) * 2 + 1];
                const uint32_t b0l = kl[nt >> 1][(nt & 1) * 2];
                const uint32_t b1l = kl[nt >> 1][(nt & 1) * 2 + 1];
                mma_tf32(sc[nt], qh[s], b0h, b1h);
                mma_tf32(sc[nt], qh[s], b0l, b1l);
                mma_tf32(sc[nt], ql[s], b0h, b1h);
            }
        }

        // ---- softmax (registers + quad shuffles) ----
        const bool maskt = (jt >= 2 * qt);
        const int qr1 = qt * 128 + wq + (lane >> 2);
        const int kcb = jt * 64 + 2 * (lane & 3);
        #pragma unroll
        for (int ri = 0; ri < 2; ri++) {
            const int qrow = qr1 + ri * 8;
            float mx = NEGINF;
            #pragma unroll
            for (int nt = 0; nt < 8; nt++) {
                float s0 = sc[nt][2 * ri] * 8.0f;
                float s1 = sc[nt][2 * ri + 1] * 8.0f;
                if (maskt) {
                    const int c = kcb + nt * 8;
                    if (c > qrow)     s0 = NEGINF;
                    if (c + 1 > qrow) s1 = NEGINF;
                }
                sc[nt][2 * ri]     = s0;
                sc[nt][2 * ri + 1] = s1;
                mx = fmaxf(mx, fmaxf(s0, s1));
            }
            mx = fmaxf(mx, __shfl_xor_sync(0xffffffffu, mx, 1));
            mx = fmaxf(mx, __shfl_xor_sync(0xffffffffu, mx, 2));
            const float mnew = fmaxf(mrow[ri], mx);
            const float alpha = __expf(mrow[ri] - mnew);
            float sum = 0.0f;
            #pragma unroll
            for (int nt = 0; nt < 8; nt++) {
                const float p0 = __expf(sc[nt][2 * ri] - mnew);
                const float p1 = __expf(sc[nt][2 * ri + 1] - mnew);
                sc[nt][2 * ri] = p0; sc[nt][2 * ri + 1] = p1;
                sum += p0 + p1;
                o[nt][2 * ri]     *= alpha;
                o[nt][2 * ri + 1] *= alpha;
            }
            sum += __shfl_xor_sync(0xffffffffu, sum, 1);
            sum += __shfl_xor_sync(0xffffffffu, sum, 2);
            lrow[ri] = lrow[ri] * alpha + sum;
            mrow[ri] = mnew;
        }

        // ---- write P (hi/lo tf32 split) to warp-private smem ----
        {
            const int rw1 = wq + (lane >> 2);
            const int kc0 = 2 * (lane & 3);
            #pragma unroll
            for (int nt = 0; nt < 8; nt++) {
                const int k = nt * 8 + kc0;
                const int kc = k & 31;
                const int base = (k >> 5) * 16384 +
                                 ((((kc >> 2) * 16)) ) + (kc & 3) * 4;
                #pragma unroll
                for (int ri = 0; ri < 2; ri++) {
                    const int rw = rw1 + ri * 8;
                    const int off = base + rw * 128;
                    const int offs = (off & ~0x70) | ((off & 0x70) ^ ((rw & 7) << 4));
                    const float p0 = sc[nt][2 * ri], p1 = sc[nt][2 * ri + 1];
                    const float h0 = tf32_rnd(p0), h1 = tf32_rnd(p1);
                    *(float2*)(fsm + FSM_PHI + offs) = make_float2(h0, h1);
                    *(float2*)(fsm + FSM_PLO + offs) =
                        make_float2(tf32_rnd(p0 - h0), tf32_rnd(p1 - h1));
                }
            }
        }
        __syncwarp();

        // ---- O += P V (3 streams) ----
        #pragma unroll
        for (int s = 0; s < 8; s++) {
            const uint32_t adP = (s >> 2) * 16384 + rA * 128 + (((s & 3) * 32) ^ aX);
            uint32_t ph[4], pl[4];
            ldsm4(ph[0], ph[1], ph[2], ph[3], sb + FSM_PHI + adP);
            ldsm4(pl[0], pl[1], pl[2], pl[3], sb + FSM_PLO + adP);
            const uint32_t cof = (s >> 2) * 8192;
            const uint32_t colb = (s & 3) * 32;
            uint32_t vh[4][4], vl[4][4];
            #pragma unroll
            for (int p = 0; p < 4; p++) {
                const uint32_t ad = cof + bR[p] + (colb ^ bX);
                ldsm4(vh[p][0], vh[p][1], vh[p][2], vh[p][3], sb + FSM_VHI + ad);
                ldsm4(vl[p][0], vl[p][1], vl[p][2], vl[p][3], sb + FSM_VLO + ad);
            }
            #pragma unroll
            for (int nt = 0; nt < 8; nt++) {
                const uint32_t b0h = vh[nt >> 1][(nt & 1) * 2];
                const uint32_t b1h = vh[nt >> 1][(nt & 1) * 2 + 1];
                const uint32_t b0l = vl[nt >> 1][(nt & 1) * 2];
                const uint32_t b1l = vl[nt >> 1][(nt & 1) * 2 + 1];
                mma_tf32(o[nt], ph, b0h, b1h);
                mma_tf32(o[nt], ph, b0l, b1l);
                mma_tf32(o[nt], pl, b0h, b1h);
            }
        }
        __syncthreads();
    }

    // ---- normalize + write ----
    const float inv0 = 1.0f / lrow[0];
    const float inv1 = 1.0f / lrow[1];
    const int gr1 = qt * 128 + wq + (lane >> 2);
    #pragma unroll
    for (int nt = 0; nt < 8; nt++) {
        const int col = nt * 8 + 2 * (lane & 3);
        *(float2*)(Og + (size_t)gr1 * E_ + col) =
            make_float2(o[nt][0] * inv0, o[nt][1] * inv0);
        *(float2*)(Og + (size_t)(gr1 + 8) * E_ + col) =
            make_float2(o[nt][2] * inv1, o[nt][3] * inv1);
    }
}

// ===========================================================================
extern "C" void kernel_launch(void* const* d_in, const int* in_sizes, int n_in,
                              void* d_out, int out_size)
{
    const float* x  = (const float*)d_in[0];
    const float* Wq = (const float*)d_in[1];
    const float* Wk = (const float*)d_in[2];
    const float* Wv = (const float*)d_in[3];
    const float* Wo = (const float*)d_in[4];
    float* out = (float*)d_out;

    cudaFuncSetAttribute(tc_gemm_qkv, cudaFuncAttributeMaxDynamicSharedMemorySize, GEMM_SMEM);
    cudaFuncSetAttribute(tc_gemm_o,   cudaFuncAttributeMaxDynamicSharedMemorySize, GEMM_SMEM);
    cudaFuncSetAttribute(flash_mma,   cudaFuncAttributeMaxDynamicSharedMemorySize, FSM_TOTAL);

    dim3 gq(24, 32);
    tc_gemm_qkv<<<gq, 256, GEMM_SMEM>>>(x, Wq, Wk, Wv);

    dim3 gt(32, 16, 2);
    v_transpose<<<gt, 256>>>();

    dim3 ga(S_ / 128, H_, B_);
    flash_mma<<<ga, 256, FSM_TOTAL>>>();

    dim3 go(8, 32);
    tc_gemm_o<<<go, 256, GEMM_SMEM>>>(Wo, out);
}

// round 7
// speedup vs baseline: 1.4203x; 1.0233x over previous
#include <cuda_runtime.h>
#include <cstdint>
#include <math.h>

#define B_ 2
#define S_ 2048
#define E_ 1024
#define H_ 16
#define D_ 64
#define M_ (B_*S_)

#define NEGINF (-1e30f)

// Scratch (allocation-free rule: __device__ globals)
__device__ float g_Q[B_*S_*E_];
__device__ float g_K[B_*S_*E_];
__device__ float g_V[B_*S_*E_];
__device__ float g_Vt[B_*H_*D_*S_];   // V transposed: [(b*H+h)][d][s]
__device__ float g_C[B_*S_*E_];

// ===========================================================================
// mma.sync helpers (family-portable sm_80+; tcgen05 unavailable: harness
// compiles virtual arch compute_100 which forbids accelerated-family PTX)
// ===========================================================================
__device__ __forceinline__ uint32_t smem_u32(const void* p) {
    uint32_t a;
    asm("{ .reg .u64 t; cvta.to.shared.u64 t, %1; cvt.u32.u64 %0, t; }"
        : "=r"(a) : "l"(p));
    return a;
}
__device__ __forceinline__ float tf32_rnd(float a) {
    uint32_t u;
    asm("cvt.rna.tf32.f32 %0, %1;" : "=r"(u) : "f"(a));
    return __uint_as_float(u);
}
__device__ __forceinline__ uint32_t tf32_bits(float a) {
    uint32_t u;
    asm("cvt.rna.tf32.f32 %0, %1;" : "=r"(u) : "f"(a));
    return u;
}
__device__ __forceinline__ void ldsm4(uint32_t& r0, uint32_t& r1,
                                      uint32_t& r2, uint32_t& r3, uint32_t addr) {
    asm volatile("ldmatrix.sync.aligned.m8n8.x4.shared.b16 {%0,%1,%2,%3}, [%4];"
                 : "=r"(r0), "=r"(r1), "=r"(r2), "=r"(r3) : "r"(addr));
}
__device__ __forceinline__ void mma_tf32(float* c, const uint32_t* a,
                                         uint32_t b0, uint32_t b1) {
    asm volatile("mma.sync.aligned.m16n8k8.row.col.f32.tf32.tf32.f32 "
                 "{%0,%1,%2,%3}, {%4,%5,%6,%7}, {%8,%9}, {%0,%1,%2,%3};"
                 : "+f"(c[0]), "+f"(c[1]), "+f"(c[2]), "+f"(c[3])
                 : "r"(a[0]), "r"(a[1]), "r"(a[2]), "r"(a[3]), "r"(b0), "r"(b1));
}

// ===========================================================================
// 3xTF32 mma.sync GEMM (NT) — unchanged from round 5/6 (passed, tensor=59%)
// ===========================================================================
#define TILE_B   16384
#define GEMM_SMEM (4 * TILE_B + 128)

__device__ __forceinline__ void tc_gemm_body(const float* __restrict__ A,
                                             const float* __restrict__ Bw,
                                             float* __restrict__ C,
                                             int bm, int bn)
{
    extern __shared__ char smraw[];
    char* smb = (char*)(((uintptr_t)smraw + 127) & ~(uintptr_t)127);
    const uint32_t sAhi = smem_u32(smb);
    const uint32_t sAlo = sAhi + TILE_B;
    const uint32_t sBhi = sAhi + 2 * TILE_B;
    const uint32_t sBlo = sAhi + 3 * TILE_B;

    const int tid  = threadIdx.x;
    const int wid  = tid >> 5;
    const int lane = tid & 31;
    const int wm = (wid >> 2) * 64;
    const int wn = (wid & 3) * 32;

    const int rlbA   = (lane & 7) + ((lane >> 3) & 1) * 8;
    const int col16A = (lane >> 4) & 1;
    const int rlbB   = (lane & 7) + ((lane >> 4) & 1) * 8;
    const int col16B = (lane >> 3) & 1;

    uint32_t aRow[4], aXor[4], bRow[2], bXor[2];
    #pragma unroll
    for (int f = 0; f < 4; f++) {
        const int r = wm + f * 16 + rlbA;
        aRow[f] = r * 128;
        aXor[f] = ((r & 7) << 4) ^ (col16A * 16);
    }
    #pragma unroll
    for (int p = 0; p < 2; p++) {
        const int r = wn + p * 16 + rlbB;
        bRow[p] = r * 128;
        bXor[p] = ((r & 7) << 4) ^ (col16B * 16);
    }

    const float* Abase = A  + (size_t)bm * E_;
    const float* Bbase = Bw + (size_t)bn * E_;

    float acc[4][4][4] = {};
    float4 rgA[4], rgB[4];

    #pragma unroll
    for (int l = 0; l < 4; l++) {
        const int idx = tid + l * 256;
        const int row = idx >> 3, c4 = idx & 7;
        rgA[l] = *(const float4*)(Abase + (size_t)row * E_ + c4 * 4);
        rgB[l] = *(const float4*)(Bbase + (size_t)row * E_ + c4 * 4);
    }

    for (int kt = 0; kt < 32; kt++) {
        #pragma unroll
        for (int l = 0; l < 4; l++) {
            const int idx = tid + l * 256;
            const int row = idx >> 3, c4 = idx & 7;
            const int off = row * 128 + (((c4 * 16) ^ ((row & 7) << 4)));
            float4 a = rgA[l];
            float hx = tf32_rnd(a.x), hy = tf32_rnd(a.y),
                  hz = tf32_rnd(a.z), hw = tf32_rnd(a.w);
            *(float4*)(smb + off) = make_float4(hx, hy, hz, hw);
            *(float4*)(smb + TILE_B + off) =
                make_float4(tf32_rnd(a.x - hx), tf32_rnd(a.y - hy),
                            tf32_rnd(a.z - hz), tf32_rnd(a.w - hw));
            float4 b = rgB[l];
            float gx = tf32_rnd(b.x), gy = tf32_rnd(b.y),
                  gz = tf32_rnd(b.z), gw = tf32_rnd(b.w);
            *(float4*)(smb + 2 * TILE_B + off) = make_float4(gx, gy, gz, gw);
            *(float4*)(smb + 3 * TILE_B + off) =
                make_float4(tf32_rnd(b.x - gx), tf32_rnd(b.y - gy),
                            tf32_rnd(b.z - gz), tf32_rnd(b.w - gw));
        }
        __syncthreads();

        if (kt + 1 < 32) {
            const int k0 = (kt + 1) * 32;
            #pragma unroll
            for (int l = 0; l < 4; l++) {
                const int idx = tid + l * 256;
                const int row = idx >> 3, c4 = idx & 7;
                rgA[l] = *(const float4*)(Abase + (size_t)row * E_ + k0 + c4 * 4);
                rgB[l] = *(const float4*)(Bbase + (size_t)row * E_ + k0 + c4 * 4);
            }
        }

        #pragma unroll
        for (int s = 0; s < 4; s++) {
            const uint32_t colb = s * 32;
            uint32_t ah[4][4], al[4][4], bh[2][4], bl[2][4];
            #pragma unroll
            for (int f = 0; f < 4; f++) {
                const uint32_t ad = aRow[f] + (colb ^ aXor[f]);
                ldsm4(ah[f][0], ah[f][1], ah[f][2], ah[f][3], sAhi + ad);
                ldsm4(al[f][0], al[f][1], al[f][2], al[f][3], sAlo + ad);
            }
            #pragma unroll
            for (int p = 0; p < 2; p++) {
                const uint32_t bd = bRow[p] + (colb ^ bXor[p]);
                ldsm4(bh[p][0], bh[p][1], bh[p][2], bh[p][3], sBhi + bd);
                ldsm4(bl[p][0], bl[p][1], bl[p][2], bl[p][3], sBlo + bd);
            }
            #pragma unroll
            for (int f = 0; f < 4; f++)
                #pragma unroll
                for (int g = 0; g < 4; g++)
                    mma_tf32(acc[f][g], ah[f], bh[g >> 1][(g & 1) * 2],
                                               bh[g >> 1][(g & 1) * 2 + 1]);
            #pragma unroll
            for (int f = 0; f < 4; f++)
                #pragma unroll
                for (int g = 0; g < 4; g++)
                    mma_tf32(acc[f][g], ah[f], bl[g >> 1][(g & 1) * 2],
                                               bl[g >> 1][(g & 1) * 2 + 1]);
            #pragma unroll
            for (int f = 0; f < 4; f++)
                #pragma unroll
                for (int g = 0; g < 4; g++)
                    mma_tf32(acc[f][g], al[f], bh[g >> 1][(g & 1) * 2],
                                               bh[g >> 1][(g & 1) * 2 + 1]);
        }
        __syncthreads();
    }

    #pragma unroll
    for (int f = 0; f < 4; f++) {
        const int r0 = bm + wm + f * 16 + (lane >> 2);
        #pragma unroll
        for (int g = 0; g < 4; g++) {
            const int cc = bn + wn + g * 8 + (lane & 3) * 2;
            *(float2*)(C + (size_t)r0 * E_ + cc) =
                make_float2(acc[f][g][0], acc[f][g][1]);
            *(float2*)(C + (size_t)(r0 + 8) * E_ + cc) =
                make_float2(acc[f][g][2], acc[f][g][3]);
        }
    }
}

__global__ __launch_bounds__(256)
void tc_gemm_qkv(const float* __restrict__ x, const float* __restrict__ Wq,
                 const float* __restrict__ Wk, const float* __restrict__ Wv)
{
    const int sel = blockIdx.x >> 3;
    const float* Bw = (sel == 0) ? Wq : (sel == 1) ? Wk : Wv;
    float* C = (sel == 0) ? g_Q : (sel == 1) ? g_K : g_V;
    tc_gemm_body(x, Bw, C, blockIdx.y * 128, (blockIdx.x & 7) * 128);
}

__global__ __launch_bounds__(256)
void tc_gemm_o(const float* __restrict__ Wo, float* __restrict__ out)
{
    tc_gemm_body(g_C, Wo, out, blockIdx.y * 128, blockIdx.x * 128);
}

// ===========================================================================
// V transpose: g_V [b][s][h*64+d] -> g_Vt [(b*H+h)][d][s]  (unchanged)
// ===========================================================================
__global__ __launch_bounds__(256)
void v_transpose()
{
    __shared__ float ts[64 * 65];
    const int st = blockIdx.x;
    const int h = blockIdx.y, b = blockIdx.z;
    const float* Vg = g_V + (size_t)b * S_ * E_ + h * D_;
    float* Vt = g_Vt + (size_t)(b * H_ + h) * D_ * S_;
    const int tid = threadIdx.x;

    #pragma unroll
    for (int l = 0; l < 4; l++) {
        const int idx = tid + l * 256;
        const int s = idx >> 4, c4 = idx & 15;
        float4 v = *(const float4*)(Vg + (size_t)(st * 64 + s) * E_ + c4 * 4);
        ts[(c4 * 4 + 0) * 65 + s] = v.x;
        ts[(c4 * 4 + 1) * 65 + s] = v.y;
        ts[(c4 * 4 + 2) * 65 + s] = v.z;
        ts[(c4 * 4 + 3) * 65 + s] = v.w;
    }
    __syncthreads();
    #pragma unroll
    for (int l = 0; l < 4; l++) {
        const int idx = tid + l * 256;
        const int d = idx >> 4, c4 = idx & 15;
        float4 w = make_float4(ts[d * 65 + c4 * 4 + 0], ts[d * 65 + c4 * 4 + 1],
                               ts[d * 65 + c4 * 4 + 2], ts[d * 65 + c4 * 4 + 3]);
        *(float4*)(Vt + (size_t)d * S_ + st * 64 + c4 * 4) = w;
    }
}

// ===========================================================================
// Flash attention, mma.sync 3xTF32, v3:
//  - P relayout C-frag -> A-frag via quad shuffles (NO smem round trip)
//  - double-buffered K/V tiles (2 x 64KB), ONE __syncthreads per KV tile
//  - Q staged once through buffer 1, then held in registers
// ===========================================================================
#define FST_STAGE 65536                 // per-stage: Khi|Klo|Vhi|Vlo 16KB each
#define FST_TOTAL (2 * FST_STAGE + 128)

__global__ __launch_bounds__(256)
void flash_mma()
{
    extern __shared__ char fraw[];
    char* fsm = (char*)(((uintptr_t)fraw + 127) & ~(uintptr_t)127);
    const uint32_t sb = smem_u32(fsm);

    const int tid = threadIdx.x, wid = tid >> 5, lane = tid & 31;
    const int qt = (S_ / 128 - 1) - (int)blockIdx.x;   // heavy tiles first
    const int h = blockIdx.y, b = blockIdx.z;

    const float* Qg  = g_Q + (size_t)b * S_ * E_ + h * D_;
    const float* Kg  = g_K + (size_t)b * S_ * E_ + h * D_;
    const float* Vtg = g_Vt + (size_t)(b * H_ + h) * D_ * S_;
    float* Og = g_C + (size_t)b * S_ * E_ + h * D_;

    const int rlbA = (lane & 7) + ((lane >> 3) & 1) * 8;
    const int c16A = (lane >> 4) & 1;
    const int rlbB = (lane & 7) + ((lane >> 4) & 1) * 8;
    const int c16B = (lane >> 3) & 1;
    const uint32_t aX = ((rlbA & 7) << 4) ^ (c16A * 16);
    const uint32_t bX = ((rlbB & 7) << 4) ^ (c16B * 16);
    const int wq = wid * 16;
    const uint32_t rA = wq + rlbA;
    uint32_t bR[4];
    #pragma unroll
    for (int p = 0; p < 4; p++) bR[p] = (p * 16 + rlbB) * 128;

    // quad-shuffle constants for the C->A fragment relayout
    const int qq   = lane & 3;
    const int srcA = (lane & ~3) | (qq >> 1);
    const int srcB = srcA + 2;
    const int selo = qq & 1;

    // ---- stage Q (hi/lo split) through buffer 1 ----
    #pragma unroll
    for (int l = 0; l < 8; l++) {
        const int idx = tid + l * 256;
        const int row = idx >> 4, c4 = idx & 15;
        float4 q = *(const float4*)(Qg + (size_t)(qt * 128 + row) * E_ + c4 * 4);
        const int off = FST_STAGE + (c4 >> 3) * 16384 + row * 128 +
                        (((c4 & 7) * 16) ^ ((row & 7) << 4));
        float hx = tf32_rnd(q.x), hy = tf32_rnd(q.y),
              hz = tf32_rnd(q.z), hw = tf32_rnd(q.w);
        *(float4*)(fsm + off) = make_float4(hx, hy, hz, hw);
        *(float4*)(fsm + 32768 + off) =
            make_float4(tf32_rnd(q.x - hx), tf32_rnd(q.y - hy),
                        tf32_rnd(q.z - hz), tf32_rnd(q.w - hw));
    }
    // ---- stage KV tile 0 into buffer 0 ----
    #pragma unroll
    for (int l = 0; l < 4; l++) {
        const int idx = tid + l * 256;
        const int row = idx >> 4, c4 = idx & 15;
        const int off = (c4 >> 3) * 8192 + row * 128 +
                        (((c4 & 7) * 16) ^ ((row & 7) << 4));
        float4 kv = *(const float4*)(Kg + (size_t)row * E_ + c4 * 4);
        float hx = tf32_rnd(kv.x), hy = tf32_rnd(kv.y),
              hz = tf32_rnd(kv.z), hw = tf32_rnd(kv.w);
        *(float4*)(fsm + off) = make_float4(hx, hy, hz, hw);
        *(float4*)(fsm + 16384 + off) =
            make_float4(tf32_rnd(kv.x - hx), tf32_rnd(kv.y - hy),
                        tf32_rnd(kv.z - hz), tf32_rnd(kv.w - hw));
        float4 vv = *(const float4*)(Vtg + (size_t)row * S_ + c4 * 4);
        float gx = tf32_rnd(vv.x), gy = tf32_rnd(vv.y),
              gz = tf32_rnd(vv.z), gw = tf32_rnd(vv.w);
        *(float4*)(fsm + 32768 + off) = make_float4(gx, gy, gz, gw);
        *(float4*)(fsm + 49152 + off) =
            make_float4(tf32_rnd(vv.x - gx), tf32_rnd(vv.y - gy),
                        tf32_rnd(vv.z - gz), tf32_rnd(vv.w - gw));
    }
    __syncthreads();

    // ---- extract Q fragments from buffer 1 ----
    uint32_t qh[8][4], ql[8][4];
    #pragma unroll
    for (int s = 0; s < 8; s++) {
        const uint32_t ad = FST_STAGE + (s >> 2) * 16384 + rA * 128 +
                            (((s & 3) * 32) ^ aX);
        ldsm4(qh[s][0], qh[s][1], qh[s][2], qh[s][3], sb + ad);
        ldsm4(ql[s][0], ql[s][1], ql[s][2], ql[s][3], sb + 32768 + ad);
    }
    __syncthreads();   // buffer 1 is now free for KV tile 1

    float o[8][4] = {};
    float mrow[2] = {NEGINF, NEGINF};
    float lrow[2] = {0.0f, 0.0f};

    const int nj = 2 * qt + 2;
    for (int jt = 0; jt < nj; jt++) {
        const uint32_t cur = (jt & 1) * FST_STAGE;
        char* curp = fsm + cur;

        // ---- prefetch next KV tile into the alternate buffer ----
        if (jt + 1 < nj) {
            char* dst = fsm + ((jt + 1) & 1) * FST_STAGE;
            const int jn = jt + 1;
            #pragma unroll
            for (int l = 0; l < 4; l++) {
                const int idx = tid + l * 256;
                const int row = idx >> 4, c4 = idx & 15;
                const int off = (c4 >> 3) * 8192 + row * 128 +
                                (((c4 & 7) * 16) ^ ((row & 7) << 4));
                float4 kv = *(const float4*)(Kg + (size_t)(jn * 64 + row) * E_ + c4 * 4);
                float hx = tf32_rnd(kv.x), hy = tf32_rnd(kv.y),
                      hz = tf32_rnd(kv.z), hw = tf32_rnd(kv.w);
                *(float4*)(dst + off) = make_float4(hx, hy, hz, hw);
                *(float4*)(dst + 16384 + off) =
                    make_float4(tf32_rnd(kv.x - hx), tf32_rnd(kv.y - hy),
                                tf32_rnd(kv.z - hz), tf32_rnd(kv.w - hw));
                float4 vv = *(const float4*)(Vtg + (size_t)row * S_ + jn * 64 + c4 * 4);
                float gx = tf32_rnd(vv.x), gy = tf32_rnd(vv.y),
                      gz = tf32_rnd(vv.z), gw = tf32_rnd(vv.w);
                *(float4*)(dst + 32768 + off) = make_float4(gx, gy, gz, gw);
                *(float4*)(dst + 49152 + off) =
                    make_float4(tf32_rnd(vv.x - gx), tf32_rnd(vv.y - gy),
                                tf32_rnd(vv.z - gz), tf32_rnd(vv.w - gw));
            }
        }

        // ---- S = Q K^T (3 streams) ----
        float sc[8][4] = {};
        #pragma unroll
        for (int s = 0; s < 8; s++) {
            const uint32_t cof = cur + (s >> 2) * 8192;
            const uint32_t colb = (s & 3) * 32;
            uint32_t kh[4][4], kl[4][4];
            #pragma unroll
            for (int p = 0; p < 4; p++) {
                const uint32_t ad = cof + bR[p] + (colb ^ bX);
                ldsm4(kh[p][0], kh[p][1], kh[p][2], kh[p][3], sb + ad);
                ldsm4(kl[p][0], kl[p][1], kl[p][2], kl[p][3], sb + 16384 + ad);
            }
            #pragma unroll
            for (int nt = 0; nt < 8; nt++) {
                const uint32_t b0h = kh[nt >> 1][(nt & 1) * 2];
                const uint32_t b1h = kh[nt >> 1][(nt & 1) * 2 + 1];
                const uint32_t b0l = kl[nt >> 1][(nt & 1) * 2];
                const uint32_t b1l = kl[nt >> 1][(nt & 1) * 2 + 1];
                mma_tf32(sc[nt], qh[s], b0h, b1h);
                mma_tf32(sc[nt], qh[s], b0l, b1l);
                mma_tf32(sc[nt], ql[s], b0h, b1h);
            }
        }

        // ---- softmax (registers + quad shuffles) ----
        const bool maskt = (jt >= 2 * qt);
        const int qr1 = qt * 128 + wq + (lane >> 2);
        const int kcb = jt * 64 + 2 * (lane & 3);
        #pragma unroll
        for (int ri = 0; ri < 2; ri++) {
            const int qrow = qr1 + ri * 8;
            float mx = NEGINF;
            #pragma unroll
            for (int nt = 0; nt < 8; nt++) {
                float s0 = sc[nt][2 * ri] * 8.0f;
                float s1 = sc[nt][2 * ri + 1] * 8.0f;
                if (maskt) {
                    const int c = kcb + nt * 8;
                    if (c > qrow)     s0 = NEGINF;
                    if (c + 1 > qrow) s1 = NEGINF;
                }
                sc[nt][2 * ri]     = s0;
                sc[nt][2 * ri + 1] = s1;
                mx = fmaxf(mx, fmaxf(s0, s1));
            }
            mx = fmaxf(mx, __shfl_xor_sync(0xffffffffu, mx, 1));
            mx = fmaxf(mx, __shfl_xor_sync(0xffffffffu, mx, 2));
            const float mnew = fmaxf(mrow[ri], mx);
            const float alpha = __expf(mrow[ri] - mnew);
            float sum = 0.0f;
            #pragma unroll
            for (int nt = 0; nt < 8; nt++) {
                const float p0 = __expf(sc[nt][2 * ri] - mnew);
                const float p1 = __expf(sc[nt][2 * ri + 1] - mnew);
                sc[nt][2 * ri] = p0; sc[nt][2 * ri + 1] = p1;
                sum += p0 + p1;
                o[nt][2 * ri]     *= alpha;
                o[nt][2 * ri + 1] *= alpha;
            }
            sum += __shfl_xor_sync(0xffffffffu, sum, 1);
            sum += __shfl_xor_sync(0xffffffffu, sum, 2);
            lrow[ri] = lrow[ri] * alpha + sum;
            mrow[ri] = mnew;
        }

        // ---- O += P V: P via quad-shuffle relayout, V from smem ----
        #pragma unroll
        for (int kk = 0; kk < 8; kk++) {
            // C-frag (rows, cols 2q/2q+1) -> A-frag (rows, cols q and q+4)
            float v00 = __shfl_sync(0xffffffffu, sc[kk][0], srcA);
            float v01 = __shfl_sync(0xffffffffu, sc[kk][1], srcA);
            float v10 = __shfl_sync(0xffffffffu, sc[kk][0], srcB);
            float v11 = __shfl_sync(0xffffffffu, sc[kk][1], srcB);
            float w00 = __shfl_sync(0xffffffffu, sc[kk][2], srcA);
            float w01 = __shfl_sync(0xffffffffu, sc[kk][3], srcA);
            float w10 = __shfl_sync(0xffffffffu, sc[kk][2], srcB);
            float w11 = __shfl_sync(0xffffffffu, sc[kk][3], srcB);
            const float a0 = selo ? v01 : v00;
            const float a2 = selo ? v11 : v10;
            const float a1 = selo ? w01 : w00;
            const float a3 = selo ? w11 : w10;
            uint32_t ph[4], pl[4];
            ph[0] = tf32_bits(a0); pl[0] = tf32_bits(a0 - __uint_as_float(ph[0]));
            ph[1] = tf32_bits(a1); pl[1] = tf32_bits(a1 - __uint_as_float(ph[1]));
            ph[2] = tf32_bits(a2); pl[2] = tf32_bits(a2 - __uint_as_float(ph[2]));
            ph[3] = tf32_bits(a3); pl[3] = tf32_bits(a3 - __uint_as_float(ph[3]));

            const uint32_t cof = cur + 32768 + (kk >> 2) * 8192;
            const uint32_t colb = (kk & 3) * 32;
            uint32_t vh[4][4], vl[4][4];
            #pragma unroll
            for (int p = 0; p < 4; p++) {
                const uint32_t ad = cof + bR[p] + (colb ^ bX);
                ldsm4(vh[p][0], vh[p][1], vh[p][2], vh[p][3], sb + ad);
                ldsm4(vl[p][0], vl[p][1], vl[p][2], vl[p][3], sb + 16384 + ad);
            }
            #pragma unroll
            for (int nt = 0; nt < 8; nt++) {
                const uint32_t b0h = vh[nt >> 1][(nt & 1) * 2];
                const uint32_t b1h = vh[nt >> 1][(nt & 1) * 2 + 1];
                const uint32_t b0l = vl[nt >> 1][(nt & 1) * 2];
                const uint32_t b1l = vl[nt >> 1][(nt & 1) * 2 + 1];
                mma_tf32(o[nt], ph, b0h, b1h);
                mma_tf32(o[nt], ph, b0l, b1l);
                mma_tf32(o[nt], pl, b0h, b1h);
            }
        }
        __syncthreads();   // single barrier per KV tile
    }

    // ---- normalize + write ----
    const float inv0 = 1.0f / lrow[0];
    const float inv1 = 1.0f / lrow[1];
    const int gr1 = qt * 128 + wq + (lane >> 2);
    #pragma unroll
    for (int nt = 0; nt < 8; nt++) {
        const int col = nt * 8 + 2 * (lane & 3);
        *(float2*)(Og + (size_t)gr1 * E_ + col) =
            make_float2(o[nt][0] * inv0, o[nt][1] * inv0);
        *(float2*)(Og + (size_t)(gr1 + 8) * E_ + col) =
            make_float2(o[nt][2] * inv1, o[nt][3] * inv1);
    }
}

// ===========================================================================
extern "C" void kernel_launch(void* const* d_in, const int* in_sizes, int n_in,
                              void* d_out, int out_size)
{
    const float* x  = (const float*)d_in[0];
    const float* Wq = (const float*)d_in[1];
    const float* Wk = (const float*)d_in[2];
    const float* Wv = (const float*)d_in[3];
    const float* Wo = (const float*)d_in[4];
    float* out = (float*)d_out;

    cudaFuncSetAttribute(tc_gemm_qkv, cudaFuncAttributeMaxDynamicSharedMemorySize, GEMM_SMEM);
    cudaFuncSetAttribute(tc_gemm_o,   cudaFuncAttributeMaxDynamicSharedMemorySize, GEMM_SMEM);
    cudaFuncSetAttribute(flash_mma,   cudaFuncAttributeMaxDynamicSharedMemorySize, FST_TOTAL);

    dim3 gq(24, 32);
    tc_gemm_qkv<<<gq, 256, GEMM_SMEM>>>(x, Wq, Wk, Wv);

    dim3 gt(32, 16, 2);
    v_transpose<<<gt, 256>>>();

    dim3 ga(S_ / 128, H_, B_);
    flash_mma<<<ga, 256, FST_TOTAL>>>();

    dim3 go(8, 32);
    tc_gemm_o<<<go, 256, GEMM_SMEM>>>(Wo, out);
}

// round 8
// speedup vs baseline: 1.6605x; 1.1691x over previous
#include <cuda_runtime.h>
#include <cstdint>
#include <math.h>

#define B_ 2
#define S_ 2048
#define E_ 1024
#define H_ 16
#define D_ 64
#define M_ (B_*S_)

#define NEGINF (-1e30f)

// Scratch (allocation-free rule: __device__ globals)
__device__ float g_Q[B_*S_*E_];
__device__ float g_K[B_*S_*E_];
__device__ float g_V[B_*S_*E_];
__device__ float g_Vt[B_*H_*D_*S_];   // V transposed: [(b*H+h)][d][s]
__device__ float g_C[B_*S_*E_];

// ===========================================================================
// mma.sync helpers (family-portable sm_80+; tcgen05 unavailable: harness
// compiles virtual arch compute_100 which forbids accelerated-family PTX)
// ===========================================================================
__device__ __forceinline__ uint32_t smem_u32(const void* p) {
    uint32_t a;
    asm("{ .reg .u64 t; cvta.to.shared.u64 t, %1; cvt.u32.u64 %0, t; }"
        : "=r"(a) : "l"(p));
    return a;
}
__device__ __forceinline__ uint32_t tf32_bits(float a) {
    uint32_t u;
    asm("cvt.rna.tf32.f32 %0, %1;" : "=r"(u) : "f"(a));
    return u;
}
__device__ __forceinline__ void ldsm4(uint32_t& r0, uint32_t& r1,
                                      uint32_t& r2, uint32_t& r3, uint32_t addr) {
    asm volatile("ldmatrix.sync.aligned.m8n8.x4.shared.b16 {%0,%1,%2,%3}, [%4];"
                 : "=r"(r0), "=r"(r1), "=r"(r2), "=r"(r3) : "r"(addr));
}
__device__ __forceinline__ void mma_tf32(float* c, const uint32_t* a,
                                         uint32_t b0, uint32_t b1) {
    asm volatile("mma.sync.aligned.m16n8k8.row.col.f32.tf32.tf32.f32 "
                 "{%0,%1,%2,%3}, {%4,%5,%6,%7}, {%8,%9}, {%0,%1,%2,%3};"
                 : "+f"(c[0]), "+f"(c[1]), "+f"(c[2]), "+f"(c[3])
                 : "r"(a[0]), "r"(a[1]), "r"(a[2]), "r"(a[3]), "r"(b0), "r"(b1));
}
// raw f32 fragment -> (hi, lo) tf32 pair
__device__ __forceinline__ void split4(const uint32_t* r, uint32_t* hi, uint32_t* lo) {
    #pragma unroll
    for (int i = 0; i < 4; i++) {
        const float v = __uint_as_float(r[i]);
        hi[i] = tf32_bits(v);
        lo[i] = tf32_bits(v - __uint_as_float(hi[i]));
    }
}
__device__ __forceinline__ void cvt4(const uint32_t* r, uint32_t* hi) {
    #pragma unroll
    for (int i = 0; i < 4; i++) hi[i] = tf32_bits(__uint_as_float(r[i]));
}

// ===========================================================================
// 3xTF32 mma.sync GEMM (NT): C[128x128] = A[M,1024] * Bw[N,1024]^T
// RAW f32 smem tiles (no pre-split), register-time hi/lo split,
// ping-pong stages, ONE barrier per K-tile.
// ===========================================================================
#define GSTAGE 32768                    // A raw 16KB + B raw 16KB
#define GEMM_SMEM (2 * GSTAGE + 128)

__device__ __forceinline__ void tc_gemm_body(const float* __restrict__ A,
                                             const float* __restrict__ Bw,
                                             float* __restrict__ C,
                                             int bm, int bn)
{
    extern __shared__ char smraw[];
    char* smb = (char*)(((uintptr_t)smraw + 127) & ~(uintptr_t)127);
    const uint32_t sbase = smem_u32(smb);

    const int tid  = threadIdx.x;
    const int wid  = tid >> 5;
    const int lane = tid & 31;
    const int wm = (wid >> 2) * 64;
    const int wn = (wid & 3) * 32;

    const int rlbA   = (lane & 7) + ((lane >> 3) & 1) * 8;
    const int col16A = (lane >> 4) & 1;
    const int rlbB   = (lane & 7) + ((lane >> 4) & 1) * 8;
    const int col16B = (lane >> 3) & 1;

    uint32_t aRow[4], aXor[4], bRow[2], bXor[2];
    #pragma unroll
    for (int f = 0; f < 4; f++) {
        const int r = wm + f * 16 + rlbA;
        aRow[f] = r * 128;
        aXor[f] = ((r & 7) << 4) ^ (col16A * 16);
    }
    #pragma unroll
    for (int p = 0; p < 2; p++) {
        const int r = wn + p * 16 + rlbB;
        bRow[p] = r * 128;
        bXor[p] = ((r & 7) << 4) ^ (col16B * 16);
    }

    const float* Abase = A  + (size_t)bm * E_;
    const float* Bbase = Bw + (size_t)bn * E_;

    float acc[4][4][4] = {};
    float4 rgA[4], rgB[4];

    // preload k-tile 0 into registers
    #pragma unroll
    for (int l = 0; l < 4; l++) {
        const int idx = tid + l * 256;
        const int row = idx >> 3, c4 = idx & 7;
        rgA[l] = *(const float4*)(Abase + (size_t)row * E_ + c4 * 4);
        rgB[l] = *(const float4*)(Bbase + (size_t)row * E_ + c4 * 4);
    }

    for (int kt = 0; kt < 32; kt++) {
        const uint32_t cur = (kt & 1) * GSTAGE;
        char* st = smb + cur;

        // STS raw (single copy)
        #pragma unroll
        for (int l = 0; l < 4; l++) {
            const int idx = tid + l * 256;
            const int row = idx >> 3, c4 = idx & 7;
            const int off = row * 128 + (((c4 * 16) ^ ((row & 7) << 4)));
            *(float4*)(st + off)         = rgA[l];
            *(float4*)(st + 16384 + off) = rgB[l];
        }
        __syncthreads();

        // prefetch next k-tile (consumed by next iteration's STS)
        if (kt + 1 < 32) {
            const int k0 = (kt + 1) * 32;
            #pragma unroll
            for (int l = 0; l < 4; l++) {
                const int idx = tid + l * 256;
                const int row = idx >> 3, c4 = idx & 7;
                rgA[l] = *(const float4*)(Abase + (size_t)row * E_ + k0 + c4 * 4);
                rgB[l] = *(const float4*)(Bbase + (size_t)row * E_ + k0 + c4 * 4);
            }
        }

        const uint32_t sAc = sbase + cur;
        const uint32_t sBc = sAc + 16384;

        #pragma unroll
        for (int s = 0; s < 4; s++) {
            const uint32_t colb = s * 32;
            uint32_t ah[4][4], al[4][4];
            #pragma unroll
            for (int f = 0; f < 4; f++) {
                uint32_t ar[4];
                ldsm4(ar[0], ar[1], ar[2], ar[3], sAc + aRow[f] + (colb ^ aXor[f]));
                split4(ar, ah[f], al[f]);
            }
            #pragma unroll
            for (int p = 0; p < 2; p++) {
                uint32_t br[4], bh2[4], bl2[4];
                ldsm4(br[0], br[1], br[2], br[3], sBc + bRow[p] + (colb ^ bXor[p]));
                split4(br, bh2, bl2);
                #pragma unroll
                for (int gg = 0; gg < 2; gg++) {
                    const int g = p * 2 + gg;
                    const uint32_t b0h = bh2[gg * 2], b1h = bh2[gg * 2 + 1];
                    const uint32_t b0l = bl2[gg * 2], b1l = bl2[gg * 2 + 1];
                    #pragma unroll
                    for (int f = 0; f < 4; f++) {
                        mma_tf32(acc[f][g], ah[f], b0h, b1h);
                        mma_tf32(acc[f][g], ah[f], b0l, b1l);
                        mma_tf32(acc[f][g], al[f], b0h, b1h);
                    }
                }
            }
        }
    }

    #pragma unroll
    for (int f = 0; f < 4; f++) {
        const int r0 = bm + wm + f * 16 + (lane >> 2);
        #pragma unroll
        for (int g = 0; g < 4; g++) {
            const int cc = bn + wn + g * 8 + (lane & 3) * 2;
            *(float2*)(C + (size_t)r0 * E_ + cc) =
                make_float2(acc[f][g][0], acc[f][g][1]);
            *(float2*)(C + (size_t)(r0 + 8) * E_ + cc) =
                make_float2(acc[f][g][2], acc[f][g][3]);
        }
    }
}

__global__ __launch_bounds__(256)
void tc_gemm_qkv(const float* __restrict__ x, const float* __restrict__ Wq,
                 const float* __restrict__ Wk, const float* __restrict__ Wv)
{
    const int sel = blockIdx.x >> 3;
    const float* Bw = (sel == 0) ? Wq : (sel == 1) ? Wk : Wv;
    float* C = (sel == 0) ? g_Q : (sel == 1) ? g_K : g_V;
    tc_gemm_body(x, Bw, C, blockIdx.y * 128, (blockIdx.x & 7) * 128);
}

__global__ __launch_bounds__(256)
void tc_gemm_o(const float* __restrict__ Wo, float* __restrict__ out)
{
    tc_gemm_body(g_C, Wo, out, blockIdx.y * 128, blockIdx.x * 128);
}

// ===========================================================================
// V transpose: g_V [b][s][h*64+d] -> g_Vt [(b*H+h)][d][s]  (unchanged)
// ===========================================================================
__global__ __launch_bounds__(256)
void v_transpose()
{
    __shared__ float ts[64 * 65];
    const int st = blockIdx.x;
    const int h = blockIdx.y, b = blockIdx.z;
    const float* Vg = g_V + (size_t)b * S_ * E_ + h * D_;
    float* Vt = g_Vt + (size_t)(b * H_ + h) * D_ * S_;
    const int tid = threadIdx.x;

    #pragma unroll
    for (int l = 0; l < 4; l++) {
        const int idx = tid + l * 256;
        const int s = idx >> 4, c4 = idx & 15;
        float4 v = *(const float4*)(Vg + (size_t)(st * 64 + s) * E_ + c4 * 4);
        ts[(c4 * 4 + 0) * 65 + s] = v.x;
        ts[(c4 * 4 + 1) * 65 + s] = v.y;
        ts[(c4 * 4 + 2) * 65 + s] = v.z;
        ts[(c4 * 4 + 3) * 65 + s] = v.w;
    }
    __syncthreads();
    #pragma unroll
    for (int l = 0; l < 4; l++) {
        const int idx = tid + l * 256;
        const int d = idx >> 4, c4 = idx & 15;
        float4 w = make_float4(ts[d * 65 + c4 * 4 + 0], ts[d * 65 + c4 * 4 + 1],
                               ts[d * 65 + c4 * 4 + 2], ts[d * 65 + c4 * 4 + 3]);
        *(float4*)(Vt + (size_t)d * S_ + st * 64 + c4 * 4) = w;
    }
}

// ===========================================================================
// Flash attention, mma.sync, v4:
//  - RAW f32 K/V in smem; hi/lo split (K) / cvt (V) at fragment time
//  - S = QK^T: 3-stream 3xTF32 (precision-critical, scores scaled x8)
//  - PV: SINGLE-stream (p_hi * v_tf32): P in [0,1], error ~3e-4 << 1e-3
//  - ping-pong KV stages (2 x 32KB), one barrier per KV tile
//  - LDG->reg at iter start, STS at next iter start (latency hidden)
// ===========================================================================
#define FST_STAGE 32768                 // per-stage: K raw 16KB + V raw 16KB
#define FST_TOTAL (2 * FST_STAGE + 128)

__global__ __launch_bounds__(256)
void flash_mma()
{
    extern __shared__ char fraw[];
    char* fsm = (char*)(((uintptr_t)fraw + 127) & ~(uintptr_t)127);
    const uint32_t sb = smem_u32(fsm);

    const int tid = threadIdx.x, wid = tid >> 5, lane = tid & 31;
    const int qt = (S_ / 128 - 1) - (int)blockIdx.x;   // heavy tiles first
    const int h = blockIdx.y, b = blockIdx.z;

    const float* Qg  = g_Q + (size_t)b * S_ * E_ + h * D_;
    const float* Kg  = g_K + (size_t)b * S_ * E_ + h * D_;
    const float* Vtg = g_Vt + (size_t)(b * H_ + h) * D_ * S_;
    float* Og = g_C + (size_t)b * S_ * E_ + h * D_;

    const int rlbA = (lane & 7) + ((lane >> 3) & 1) * 8;
    const int c16A = (lane >> 4) & 1;
    const int rlbB = (lane & 7) + ((lane >> 4) & 1) * 8;
    const int c16B = (lane >> 3) & 1;
    const uint32_t aX = ((rlbA & 7) << 4) ^ (c16A * 16);
    const uint32_t bX = ((rlbB & 7) << 4) ^ (c16B * 16);
    const int wq = wid * 16;
    const uint32_t rA = wq + rlbA;
    uint32_t bR[4];
    #pragma unroll
    for (int p = 0; p < 4; p++) bR[p] = (p * 16 + rlbB) * 128;

    // quad-shuffle constants for the C->A fragment relayout
    const int qq   = lane & 3;
    const int srcA = (lane & ~3) | (qq >> 1);
    const int srcB = srcA + 2;
    const int selo = qq & 1;

    // ---- preload KV tile 0 into registers ----
    float4 rgK[4], rgV[4];
    #pragma unroll
    for (int l = 0; l < 4; l++) {
        const int idx = tid + l * 256;
        const int row = idx >> 4, c4 = idx & 15;
        rgK[l] = *(const float4*)(Kg + (size_t)row * E_ + c4 * 4);
        rgV[l] = *(const float4*)(Vtg + (size_t)row * S_ + c4 * 4);
    }

    // ---- stage Q RAW through stage-1 buffer ----
    #pragma unroll
    for (int l = 0; l < 8; l++) {
        const int idx = tid + l * 256;
        const int row = idx >> 4, c4 = idx & 15;
        float4 q = *(const float4*)(Qg + (size_t)(qt * 128 + row) * E_ + c4 * 4);
        const int off = FST_STAGE + (c4 >> 3) * 16384 + row * 128 +
                        (((c4 & 7) * 16) ^ ((row & 7) << 4));
        *(float4*)(fsm + off) = q;
    }
    __syncthreads();

    // ---- extract raw Q fragments (split per-use later) ----
    uint32_t qr[8][4];
    #pragma unroll
    for (int s = 0; s < 8; s++) {
        const uint32_t ad = FST_STAGE + (s >> 2) * 16384 + rA * 128 +
                            (((s & 3) * 32) ^ aX);
        ldsm4(qr[s][0], qr[s][1], qr[s][2], qr[s][3], sb + ad);
    }
    __syncthreads();   // stage 1 free again

    float o[8][4] = {};
    float mrow[2] = {NEGINF, NEGINF};
    float lrow[2] = {0.0f, 0.0f};

    const int nj = 2 * qt + 2;
    for (int jt = 0; jt < nj; jt++) {
        const uint32_t cur = (jt & 1) * FST_STAGE;
        char* st = fsm + cur;

        // ---- STS this tile's registers (raw) ----
        #pragma unroll
        for (int l = 0; l < 4; l++) {
            const int idx = tid + l * 256;
            const int row = idx >> 4, c4 = idx & 15;
            const int off = (c4 >> 3) * 8192 + row * 128 +
                            (((c4 & 7) * 16) ^ ((row & 7) << 4));
            *(float4*)(st + off)         = rgK[l];
            *(float4*)(st + 16384 + off) = rgV[l];
        }
        __syncthreads();

        // ---- LDG next KV tile into registers ----
        if (jt + 1 < nj) {
            const int jn = jt + 1;
            #pragma unroll
            for (int l = 0; l < 4; l++) {
                const int idx = tid + l * 256;
                const int row = idx >> 4, c4 = idx & 15;
                rgK[l] = *(const float4*)(Kg + (size_t)(jn * 64 + row) * E_ + c4 * 4);
                rgV[l] = *(const float4*)(Vtg + (size_t)row * S_ + jn * 64 + c4 * 4);
            }
        }

        // ---- S = Q K^T (3 streams; K split at fragment time) ----
        float sc[8][4] = {};
        #pragma unroll
        for (int s = 0; s < 8; s++) {
            const uint32_t cof = cur + (s >> 2) * 8192;
            const uint32_t colb = (s & 3) * 32;
            uint32_t qh[4], ql[4];
            split4(qr[s], qh, ql);
            uint32_t kh[4][4], kl[4][4];
            #pragma unroll
            for (int p = 0; p < 4; p++) {
                uint32_t kr[4];
                ldsm4(kr[0], kr[1], kr[2], kr[3], sb + cof + bR[p] + (colb ^ bX));
                split4(kr, kh[p], kl[p]);
            }
            #pragma unroll
            for (int nt = 0; nt < 8; nt++) {
                const uint32_t b0h = kh[nt >> 1][(nt & 1) * 2];
                const uint32_t b1h = kh[nt >> 1][(nt & 1) * 2 + 1];
                const uint32_t b0l = kl[nt >> 1][(nt & 1) * 2];
                const uint32_t b1l = kl[nt >> 1][(nt & 1) * 2 + 1];
                mma_tf32(sc[nt], qh, b0h, b1h);
                mma_tf32(sc[nt], qh, b0l, b1l);
                mma_tf32(sc[nt], ql, b0h, b1h);
            }
        }

        // ---- softmax (registers + quad shuffles) ----
        const bool maskt = (jt >= 2 * qt);
        const int qr1 = qt * 128 + wq + (lane >> 2);
        const int kcb = jt * 64 + 2 * (lane & 3);
        #pragma unroll
        for (int ri = 0; ri < 2; ri++) {
            const int qrow = qr1 + ri * 8;
            float mx = NEGINF;
            #pragma unroll
            for (int nt = 0; nt < 8; nt++) {
                float s0 = sc[nt][2 * ri] * 8.0f;
                float s1 = sc[nt][2 * ri + 1] * 8.0f;
                if (maskt) {
                    const int c = kcb + nt * 8;
                    if (c > qrow)     s0 = NEGINF;
                    if (c + 1 > qrow) s1 = NEGINF;
                }
                sc[nt][2 * ri]     = s0;
                sc[nt][2 * ri + 1] = s1;
                mx = fmaxf(mx, fmaxf(s0, s1));
            }
            mx = fmaxf(mx, __shfl_xor_sync(0xffffffffu, mx, 1));
            mx = fmaxf(mx, __shfl_xor_sync(0xffffffffu, mx, 2));
            const float mnew = fmaxf(mrow[ri], mx);
            const float alpha = __expf(mrow[ri] - mnew);
            float sum = 0.0f;
            #pragma unroll
            for (int nt = 0; nt < 8; nt++) {
                const float p0 = __expf(sc[nt][2 * ri] - mnew);
                const float p1 = __expf(sc[nt][2 * ri + 1] - mnew);
                sc[nt][2 * ri] = p0; sc[nt][2 * ri + 1] = p1;
                sum += p0 + p1;
                o[nt][2 * ri]     *= alpha;
                o[nt][2 * ri + 1] *= alpha;
            }
            sum += __shfl_xor_sync(0xffffffffu, sum, 1);
            sum += __shfl_xor_sync(0xffffffffu, sum, 2);
            lrow[ri] = lrow[ri] * alpha + sum;
            mrow[ri] = mnew;
        }

        // ---- O += P V: P relayout via quad shuffles, SINGLE tf32 stream ----
        #pragma unroll
        for (int kk = 0; kk < 8; kk++) {
            float v00 = __shfl_sync(0xffffffffu, sc[kk][0], srcA);
            float v01 = __shfl_sync(0xffffffffu, sc[kk][1], srcA);
            float v10 = __shfl_sync(0xffffffffu, sc[kk][0], srcB);
            float v11 = __shfl_sync(0xffffffffu, sc[kk][1], srcB);
            float w00 = __shfl_sync(0xffffffffu, sc[kk][2], srcA);
            float w01 = __shfl_sync(0xffffffffu, sc[kk][3], srcA);
            float w10 = __shfl_sync(0xffffffffu, sc[kk][2], srcB);
            float w11 = __shfl_sync(0xffffffffu, sc[kk][3], srcB);
            uint32_t ph[4];
            ph[0] = tf32_bits(selo ? v01 : v00);
            ph[1] = tf32_bits(selo ? w01 : w00);
            ph[2] = tf32_bits(selo ? v11 : v10);
            ph[3] = tf32_bits(selo ? w11 : w10);

            const uint32_t cof = cur + 16384 + (kk >> 2) * 8192;
            const uint32_t colb = (kk & 3) * 32;
            uint32_t vh[4][4];
            #pragma unroll
            for (int p = 0; p < 4; p++) {
                uint32_t vr[4];
                ldsm4(vr[0], vr[1], vr[2], vr[3], sb + cof + bR[p] + (colb ^ bX));
                cvt4(vr, vh[p]);
            }
            #pragma unroll
            for (int nt = 0; nt < 8; nt++)
                mma_tf32(o[nt], ph, vh[nt >> 1][(nt & 1) * 2],
                                    vh[nt >> 1][(nt & 1) * 2 + 1]);
        }
        __syncthreads();
    }

    // ---- normalize + write ----
    const float inv0 = 1.0f / lrow[0];
    const float inv1 = 1.0f / lrow[1];
    const int gr1 = qt * 128 + wq + (lane >> 2);
    #pragma unroll
    for (int nt = 0; nt < 8; nt++) {
        const int col = nt * 8 + 2 * (lane & 3);
        *(float2*)(Og + (size_t)gr1 * E_ + col) =
            make_float2(o[nt][0] * inv0, o[nt][1] * inv0);
        *(float2*)(Og + (size_t)(gr1 + 8) * E_ + col) =
            make_float2(o[nt][2] * inv1, o[nt][3] * inv1);
    }
}

// ===========================================================================
extern "C" void kernel_launch(void* const* d_in, const int* in_sizes, int n_in,
                              void* d_out, int out_size)
{
    const float* x  = (const float*)d_in[0];
    const float* Wq = (const float*)d_in[1];
    const float* Wk = (const float*)d_in[2];
    const float* Wv = (const float*)d_in[3];
    const float* Wo = (const float*)d_in[4];
    float* out = (float*)d_out;

    cudaFuncSetAttribute(tc_gemm_qkv, cudaFuncAttributeMaxDynamicSharedMemorySize, GEMM_SMEM);
    cudaFuncSetAttribute(tc_gemm_o,   cudaFuncAttributeMaxDynamicSharedMemorySize, GEMM_SMEM);
    cudaFuncSetAttribute(flash_mma,   cudaFuncAttributeMaxDynamicSharedMemorySize, FST_TOTAL);

    dim3 gq(24, 32);
    tc_gemm_qkv<<<gq, 256, GEMM_SMEM>>>(x, Wq, Wk, Wv);

    dim3 gt(32, 16, 2);
    v_transpose<<<gt, 256>>>();

    dim3 ga(S_ / 128, H_, B_);
    flash_mma<<<ga, 256, FST_TOTAL>>>();

    dim3 go(8, 32);
    tc_gemm_o<<<go, 256, GEMM_SMEM>>>(Wo, out);
}

// round 10
// speedup vs baseline: 1.7439x; 1.0502x over previous
#include <cuda_runtime.h>
#include <cstdint>
#include <math.h>

#define B_ 2
#define S_ 2048
#define E_ 1024
#define H_ 16
#define D_ 64
#define M_ (B_*S_)

#define NEGINF (-1e30f)

// Scratch (allocation-free rule: __device__ globals)
__device__ float g_Q[B_*S_*E_];
__device__ float g_K[B_*S_*E_];
__device__ float g_V[B_*S_*E_];
__device__ float g_Vt[B_*H_*D_*S_];   // V transposed: [(b*H+h)][d][s]
__device__ float g_C[B_*S_*E_];

// ===========================================================================
// mma.sync + cp.async helpers (family-portable sm_80+; tcgen05 unavailable:
// harness targets virtual arch compute_100, forbidding accelerated-family PTX)
// ===========================================================================
__device__ __forceinline__ uint32_t smem_u32(const void* p) {
    uint32_t a;
    asm("{ .reg .u64 t; cvta.to.shared.u64 t, %1; cvt.u32.u64 %0, t; }"
        : "=r"(a) : "l"(p));
    return a;
}
__device__ __forceinline__ uint32_t tf32_bits(float a) {
    uint32_t u;
    asm("cvt.rna.tf32.f32 %0, %1;" : "=r"(u) : "f"(a));
    return u;
}
__device__ __forceinline__ void ldsm4(uint32_t& r0, uint32_t& r1,
                                      uint32_t& r2, uint32_t& r3, uint32_t addr) {
    asm volatile("ldmatrix.sync.aligned.m8n8.x4.shared.b16 {%0,%1,%2,%3}, [%4];"
                 : "=r"(r0), "=r"(r1), "=r"(r2), "=r"(r3) : "r"(addr));
}
__device__ __forceinline__ void mma_tf32(float* c, const uint32_t* a,
                                         uint32_t b0, uint32_t b1) {
    asm volatile("mma.sync.aligned.m16n8k8.row.col.f32.tf32.tf32.f32 "
                 "{%0,%1,%2,%3}, {%4,%5,%6,%7}, {%8,%9}, {%0,%1,%2,%3};"
                 : "+f"(c[0]), "+f"(c[1]), "+f"(c[2]), "+f"(c[3])
                 : "r"(a[0]), "r"(a[1]), "r"(a[2]), "r"(a[3]), "r"(b0), "r"(b1));
}
__device__ __forceinline__ void split4(const uint32_t* r, uint32_t* hi, uint32_t* lo) {
    #pragma unroll
    for (int i = 0; i < 4; i++) {
        const float v = __uint_as_float(r[i]);
        hi[i] = tf32_bits(v);
        lo[i] = tf32_bits(v - __uint_as_float(hi[i]));
    }
}
__device__ __forceinline__ void cvt4(const uint32_t* r, uint32_t* hi) {
    #pragma unroll
    for (int i = 0; i < 4; i++) hi[i] = tf32_bits(__uint_as_float(r[i]));
}
__device__ __forceinline__ void cpasync16(uint32_t dst, const void* src) {
    asm volatile("cp.async.cg.shared.global [%0], [%1], 16;" :: "r"(dst), "l"(src));
}
__device__ __forceinline__ void cpasync_commit() {
    asm volatile("cp.async.commit_group;");
}
template<int N> __device__ __forceinline__ void cpasync_wait() {
    asm volatile("cp.async.wait_group %0;" :: "n"(N));
}

// ===========================================================================
// 3xTF32 mma.sync GEMM (NT): C[128x128] = A[M,1024] * Bw[N,1024]^T
// cp.async 3-stage ring (raw f32 tiles), register-time hi/lo split,
// ONE barrier per K-tile.
// ===========================================================================
#define GSTAGE 32768                    // A raw 16KB + B raw 16KB
#define GNS 3
#define GEMM_SMEM (GNS * GSTAGE + 128)

__device__ __forceinline__ void gemm_issue(uint32_t sdst,
                                           const float* __restrict__ Abase,
                                           const float* __restrict__ Bbase,
                                           int k0, int tid)
{
    #pragma unroll
    for (int l = 0; l < 4; l++) {
        const int idx = tid + l * 256;
        const int row = idx >> 3, c4 = idx & 7;
        const int off = row * 128 + ((c4 * 16) ^ ((row & 7) << 4));
        cpasync16(sdst + off,         Abase + (size_t)row * E_ + k0 + c4 * 4);
        cpasync16(sdst + 16384 + off, Bbase + (size_t)row * E_ + k0 + c4 * 4);
    }
    cpasync_commit();
}

__device__ __forceinline__ void tc_gemm_body(const float* __restrict__ A,
                                             const float* __restrict__ Bw,
                                             float* __restrict__ C,
                                             int bm, int bn)
{
    extern __shared__ char smraw[];
    char* smb = (char*)(((uintptr_t)smraw + 127) & ~(uintptr_t)127);
    const uint32_t sbase = smem_u32(smb);

    const int tid  = threadIdx.x;
    const int wid  = tid >> 5;
    const int lane = tid & 31;
    const int wm = (wid >> 2) * 64;
    const int wn = (wid & 3) * 32;

    const int rlbA   = (lane & 7) + ((lane >> 3) & 1) * 8;
    const int col16A = (lane >> 4) & 1;
    const int rlbB   = (lane & 7) + ((lane >> 4) & 1) * 8;
    const int col16B = (lane >> 3) & 1;

    uint32_t aRow[4], aXor[4], bRow[2], bXor[2];
    #pragma unroll
    for (int f = 0; f < 4; f++) {
        const int r = wm + f * 16 + rlbA;
        aRow[f] = r * 128;
        aXor[f] = ((r & 7) << 4) ^ (col16A * 16);
    }
    #pragma unroll
    for (int p = 0; p < 2; p++) {
        const int r = wn + p * 16 + rlbB;
        bRow[p] = r * 128;
        bXor[p] = ((r & 7) << 4) ^ (col16B * 16);
    }

    const float* Abase = A  + (size_t)bm * E_;
    const float* Bbase = Bw + (size_t)bn * E_;

    float acc[4][4][4] = {};

    // prologue: stages 0 and 1 in flight
    gemm_issue(sbase,          Abase, Bbase, 0,  tid);
    gemm_issue(sbase + GSTAGE, Abase, Bbase, 32, tid);

    for (int kt = 0; kt < 32; kt++) {
        cpasync_wait<1>();          // stage kt arrived (for this thread)
        __syncthreads();            // ... and for all threads

        // keep group-count invariant: one commit per iteration
        if (kt + 2 < 32)
            gemm_issue(sbase + ((kt + 2) % GNS) * GSTAGE, Abase, Bbase,
                       (kt + 2) * 32, tid);
        else
            cpasync_commit();       // empty group

        const uint32_t sAc = sbase + (kt % GNS) * GSTAGE;
        const uint32_t sBc = sAc + 16384;

        #pragma unroll
        for (int s = 0; s < 4; s++) {
            const uint32_t colb = s * 32;
            uint32_t ah[4][4], al[4][4];
            #pragma unroll
            for (int f = 0; f < 4; f++) {
                uint32_t ar[4];
                ldsm4(ar[0], ar[1], ar[2], ar[3], sAc + aRow[f] + (colb ^ aXor[f]));
                split4(ar, ah[f], al[f]);
            }
            #pragma unroll
            for (int p = 0; p < 2; p++) {
                uint32_t br[4], bh2[4], bl2[4];
                ldsm4(br[0], br[1], br[2], br[3], sBc + bRow[p] + (colb ^ bXor[p]));
                split4(br, bh2, bl2);
                #pragma unroll
                for (int gg = 0; gg < 2; gg++) {
                    const int g = p * 2 + gg;
                    const uint32_t b0h = bh2[gg * 2], b1h = bh2[gg * 2 + 1];
                    const uint32_t b0l = bl2[gg * 2], b1l = bl2[gg * 2 + 1];
                    #pragma unroll
                    for (int f = 0; f < 4; f++) {
                        mma_tf32(acc[f][g], ah[f], b0h, b1h);
                        mma_tf32(acc[f][g], ah[f], b0l, b1l);
                        mma_tf32(acc[f][g], al[f], b0h, b1h);
                    }
                }
            }
        }
    }

    #pragma unroll
    for (int f = 0; f < 4; f++) {
        const int r0 = bm + wm + f * 16 + (lane >> 2);
        #pragma unroll
        for (int g = 0; g < 4; g++) {
            const int cc = bn + wn + g * 8 + (lane & 3) * 2;
            *(float2*)(C + (size_t)r0 * E_ + cc) =
                make_float2(acc[f][g][0], acc[f][g][1]);
            *(float2*)(C + (size_t)(r0 + 8) * E_ + cc) =
                make_float2(acc[f][g][2], acc[f][g][3]);
        }
    }
}

__global__ __launch_bounds__(256)
void tc_gemm_qkv(const float* __restrict__ x, const float* __restrict__ Wq,
                 const float* __restrict__ Wk, const float* __restrict__ Wv)
{
    const int sel = blockIdx.x >> 3;
    const float* Bw = (sel == 0) ? Wq : (sel == 1) ? Wk : Wv;
    float* C = (sel == 0) ? g_Q : (sel == 1) ? g_K : g_V;
    tc_gemm_body(x, Bw, C, blockIdx.y * 128, (blockIdx.x & 7) * 128);
}

__global__ __launch_bounds__(256)
void tc_gemm_o(const float* __restrict__ Wo, float* __restrict__ out)
{
    tc_gemm_body(g_C, Wo, out, blockIdx.y * 128, blockIdx.x * 128);
}

// ===========================================================================
// V transpose: g_V [b][s][h*64+d] -> g_Vt [(b*H+h)][d][s]  (unchanged)
// ===========================================================================
__global__ __launch_bounds__(256)
void v_transpose()
{
    __shared__ float ts[64 * 65];
    const int st = blockIdx.x;
    const int h = blockIdx.y, b = blockIdx.z;
    const float* Vg = g_V + (size_t)b * S_ * E_ + h * D_;
    float* Vt = g_Vt + (size_t)(b * H_ + h) * D_ * S_;
    const int tid = threadIdx.x;

    #pragma unroll
    for (int l = 0; l < 4; l++) {
        const int idx = tid + l * 256;
        const int s = idx >> 4, c4 = idx & 15;
        float4 v = *(const float4*)(Vg + (size_t)(st * 64 + s) * E_ + c4 * 4);
        ts[(c4 * 4 + 0) * 65 + s] = v.x;
        ts[(c4 * 4 + 1) * 65 + s] = v.y;
        ts[(c4 * 4 + 2) * 65 + s] = v.z;
        ts[(c4 * 4 + 3) * 65 + s] = v.w;
    }
    __syncthreads();
    #pragma unroll
    for (int l = 0; l < 4; l++) {
        const int idx = tid + l * 256;
        const int d = idx >> 4, c4 = idx & 15;
        float4 w = make_float4(ts[d * 65 + c4 * 4 + 0], ts[d * 65 + c4 * 4 + 1],
                               ts[d * 65 + c4 * 4 + 2], ts[d * 65 + c4 * 4 + 3]);
        *(float4*)(Vt + (size_t)d * S_ + st * 64 + c4 * 4) = w;
    }
}

// ===========================================================================
// Flash attention, mma.sync, v5: cp.async 2-stage K/V ring.
//  - RAW f32 K/V; K split / V cvt at fragment time
//  - S = QK^T: 3-stream;  PV: single-stream (P in [0,1])
//  - one barrier per KV tile
// ===========================================================================
#define FST_STAGE 32768                 // per-stage: K raw 16KB + V raw 16KB
#define FST_TOTAL (2 * FST_STAGE + 128)

__device__ __forceinline__ void flash_issue_kv(uint32_t sdst,
                                               const float* __restrict__ Kg,
                                               const float* __restrict__ Vtg,
                                               int jt, int tid)
{
    #pragma unroll
    for (int l = 0; l < 4; l++) {
        const int idx = tid + l * 256;
        const int row = idx >> 4, c4 = idx & 15;
        const int off = (c4 >> 3) * 8192 + row * 128 +
                        (((c4 & 7) * 16) ^ ((row & 7) << 4));
        cpasync16(sdst + off,         Kg + (size_t)(jt * 64 + row) * E_ + c4 * 4);
        cpasync16(sdst + 16384 + off, Vtg + (size_t)row * S_ + jt * 64 + c4 * 4);
    }
    cpasync_commit();
}

__global__ __launch_bounds__(256)
void flash_mma()
{
    extern __shared__ char fraw[];
    char* fsm = (char*)(((uintptr_t)fraw + 127) & ~(uintptr_t)127);
    const uint32_t sb = smem_u32(fsm);

    const int tid = threadIdx.x, wid = tid >> 5, lane = tid & 31;
    const int qt = (S_ / 128 - 1) - (int)blockIdx.x;   // heavy tiles first
    const int h = blockIdx.y, b = blockIdx.z;

    const float* Qg  = g_Q + (size_t)b * S_ * E_ + h * D_;
    const float* Kg  = g_K + (size_t)b * S_ * E_ + h * D_;
    const float* Vtg = g_Vt + (size_t)(b * H_ + h) * D_ * S_;
    float* Og = g_C + (size_t)b * S_ * E_ + h * D_;

    const int rlbA = (lane & 7) + ((lane >> 3) & 1) * 8;
    const int c16A = (lane >> 4) & 1;
    const int rlbB = (lane & 7) + ((lane >> 4) & 1) * 8;
    const int c16B = (lane >> 3) & 1;
    const uint32_t aX = ((rlbA & 7) << 4) ^ (c16A * 16);
    const uint32_t bX = ((rlbB & 7) << 4) ^ (c16B * 16);
    const int wq = wid * 16;
    const uint32_t rA = wq + rlbA;
    uint32_t bR[4];
    #pragma unroll
    for (int p = 0; p < 4; p++) bR[p] = (p * 16 + rlbB) * 128;

    // quad-shuffle constants for the C->A fragment relayout
    const int qq   = lane & 3;
    const int srcA = (lane & ~3) | (qq >> 1);
    const int srcB = srcA + 2;
    const int selo = qq & 1;

    // ---- prologue: KV tile 0 in flight; stage Q raw through stage-1 buffer
    flash_issue_kv(sb, Kg, Vtg, 0, tid);
    #pragma unroll
    for (int l = 0; l < 8; l++) {
        const int idx = tid + l * 256;
        const int row = idx >> 4, c4 = idx & 15;
        float4 q = *(const float4*)(Qg + (size_t)(qt * 128 + row) * E_ + c4 * 4);
        const int off = FST_STAGE + (c4 >> 3) * 16384 + row * 128 +
                        (((c4 & 7) * 16) ^ ((row & 7) << 4));
        *(float4*)(fsm + off) = q;
    }
    __syncthreads();
    uint32_t qr[8][4];
    #pragma unroll
    for (int s = 0; s < 8; s++) {
        const uint32_t ad = FST_STAGE + (s >> 2) * 16384 + rA * 128 +
                            (((s & 3) * 32) ^ aX);
        ldsm4(qr[s][0], qr[s][1], qr[s][2], qr[s][3], sb + ad);
    }
    __syncthreads();   // stage 1 is free for KV tile 1

    float o[8][4] = {};
    float mrow[2] = {NEGINF, NEGINF};
    float lrow[2] = {0.0f, 0.0f};

    const int nj = 2 * qt + 2;
    for (int jt = 0; jt < nj; jt++) {
        cpasync_wait<0>();          // KV tile jt arrived (this thread)
        __syncthreads();            // ... and all threads; prev compute done

        if (jt + 1 < nj)
            flash_issue_kv(sb + ((jt + 1) & 1) * FST_STAGE, Kg, Vtg, jt + 1, tid);

        const uint32_t cur = (jt & 1) * FST_STAGE;

        // ---- S = Q K^T (3 streams; operands split at fragment time) ----
        float sc[8][4] = {};
        #pragma unroll
        for (int s = 0; s < 8; s++) {
            const uint32_t cof = cur + (s >> 2) * 8192;
            const uint32_t colb = (s & 3) * 32;
            uint32_t qh[4], ql[4];
            split4(qr[s], qh, ql);
            uint32_t kh[4][4], kl[4][4];
            #pragma unroll
            for (int p = 0; p < 4; p++) {
                uint32_t kr[4];
                ldsm4(kr[0], kr[1], kr[2], kr[3], sb + cof + bR[p] + (colb ^ bX));
                split4(kr, kh[p], kl[p]);
            }
            #pragma unroll
            for (int nt = 0; nt < 8; nt++) {
                const uint32_t b0h = kh[nt >> 1][(nt & 1) * 2];
                const uint32_t b1h = kh[nt >> 1][(nt & 1) * 2 + 1];
                const uint32_t b0l = kl[nt >> 1][(nt & 1) * 2];
                const uint32_t b1l = kl[nt >> 1][(nt & 1) * 2 + 1];
                mma_tf32(sc[nt], qh, b0h, b1h);
                mma_tf32(sc[nt], qh, b0l, b1l);
                mma_tf32(sc[nt], ql, b0h, b1h);
            }
        }

        // ---- softmax (registers + quad shuffles) ----
        const bool maskt = (jt >= 2 * qt);
        const int qr1 = qt * 128 + wq + (lane >> 2);
        const int kcb = jt * 64 + 2 * (lane & 3);
        #pragma unroll
        for (int ri = 0; ri < 2; ri++) {
            const int qrow = qr1 + ri * 8;
            float mx = NEGINF;
            #pragma unroll
            for (int nt = 0; nt < 8; nt++) {
                float s0 = sc[nt][2 * ri] * 8.0f;
                float s1 = sc[nt][2 * ri + 1] * 8.0f;
                if (maskt) {
                    const int c = kcb + nt * 8;
                    if (c > qrow)     s0 = NEGINF;
                    if (c + 1 > qrow) s1 = NEGINF;
                }
                sc[nt][2 * ri]     = s0;
                sc[nt][2 * ri + 1] = s1;
                mx = fmaxf(mx, fmaxf(s0, s1));
            }
            mx = fmaxf(mx, __shfl_xor_sync(0xffffffffu, mx, 1));
            mx = fmaxf(mx, __shfl_xor_sync(0xffffffffu, mx, 2));
            const float mnew = fmaxf(mrow[ri], mx);
            const float alpha = __expf(mrow[ri] - mnew);
            float sum = 0.0f;
            #pragma unroll
            for (int nt = 0; nt < 8; nt++) {
                const float p0 = __expf(sc[nt][2 * ri] - mnew);
                const float p1 = __expf(sc[nt][2 * ri + 1] - mnew);
                sc[nt][2 * ri] = p0; sc[nt][2 * ri + 1] = p1;
                sum += p0 + p1;
                o[nt][2 * ri]     *= alpha;
                o[nt][2 * ri + 1] *= alpha;
            }
            sum += __shfl_xor_sync(0xffffffffu, sum, 1);
            sum += __shfl_xor_sync(0xffffffffu, sum, 2);
            lrow[ri] = lrow[ri] * alpha + sum;
            mrow[ri] = mnew;
        }

        // ---- O += P V: P relayout via quad shuffles, single tf32 stream ----
        #pragma unroll
        for (int kk = 0; kk < 8; kk++) {
            float v00 = __shfl_sync(0xffffffffu, sc[kk][0], srcA);
            float v01 = __shfl_sync(0xffffffffu, sc[kk][1], srcA);
            float v10 = __shfl_sync(0xffffffffu, sc[kk][0], srcB);
            float v11 = __shfl_sync(0xffffffffu, sc[kk][1], srcB);
            float w00 = __shfl_sync(0xffffffffu, sc[kk][2], srcA);
            float w01 = __shfl_sync(0xffffffffu, sc[kk][3], srcA);
            float w10 = __shfl_sync(0xffffffffu, sc[kk][2], srcB);
            float w11 = __shfl_sync(0xffffffffu, sc[kk][3], srcB);
            uint32_t ph[4];
            ph[0] = tf32_bits(selo ? v01 : v00);
            ph[1] = tf32_bits(selo ? w01 : w00);
            ph[2] = tf32_bits(selo ? v11 : v10);
            ph[3] = tf32_bits(selo ? w11 : w10);

            const uint32_t cof = cur + 16384 + (kk >> 2) * 8192;
            const uint32_t colb = (kk & 3) * 32;
            uint32_t vh[4][4];
            #pragma unroll
            for (int p = 0; p < 4; p++) {
                uint32_t vr[4];
                ldsm4(vr[0], vr[1], vr[2], vr[3], sb + cof + bR[p] + (colb ^ bX));
                cvt4(vr, vh[p]);
            }
            #pragma unroll
            for (int nt = 0; nt < 8; nt++)
                mma_tf32(o[nt], ph, vh[nt >> 1][(nt & 1) * 2],
                                    vh[nt >> 1][(nt & 1) * 2 + 1]);
        }
    }

    // ---- normalize + write ----
    const float inv0 = 1.0f / lrow[0];
    const float inv1 = 1.0f / lrow[1];
    const int gr1 = qt * 128 + wq + (lane >> 2);
    #pragma unroll
    for (int nt = 0; nt < 8; nt++) {
        const int col = nt * 8 + 2 * (lane & 3);
        *(float2*)(Og + (size_t)gr1 * E_ + col) =
            make_float2(o[nt][0] * inv0, o[nt][1] * inv0);
        *(float2*)(Og + (size_t)(gr1 + 8) * E_ + col) =
            make_float2(o[nt][2] * inv1, o[nt][3] * inv1);
    }
}

// ===========================================================================
extern "C" void kernel_launch(void* const* d_in, const int* in_sizes, int n_in,
                              void* d_out, int out_size)
{
    const float* x  = (const float*)d_in[0];
    const float* Wq = (const float*)d_in[1];
    const float* Wk = (const float*)d_in[2];
    const float* Wv = (const float*)d_in[3];
    const float* Wo = (const float*)d_in[4];
    float* out = (float*)d_out;

    cudaFuncSetAttribute(tc_gemm_qkv, cudaFuncAttributeMaxDynamicSharedMemorySize, GEMM_SMEM);
    cudaFuncSetAttribute(tc_gemm_o,   cudaFuncAttributeMaxDynamicSharedMemorySize, GEMM_SMEM);
    cudaFuncSetAttribute(flash_mma,   cudaFuncAttributeMaxDynamicSharedMemorySize, FST_TOTAL);

    dim3 gq(24, 32);
    tc_gemm_qkv<<<gq, 256, GEMM_SMEM>>>(x, Wq, Wk, Wv);

    dim3 gt(32, 16, 2);
    v_transpose<<<gt, 256>>>();

    dim3 ga(S_ / 128, H_, B_);
    flash_mma<<<ga, 256, FST_TOTAL>>>();

    dim3 go(8, 32);
    tc_gemm_o<<<go, 256, GEMM_SMEM>>>(Wo, out);
}

// round 11
// speedup vs baseline: 2.5144x; 1.4419x over previous
#include <cuda_runtime.h>
#include <cstdint>
#include <math.h>

#define B_ 2
#define S_ 2048
#define E_ 1024
#define H_ 16
#define D_ 64
#define M_ (B_*S_)

#define NEGINF (-1e30f)

// Scratch (allocation-free rule: __device__ globals)
__device__ float g_Q[B_*S_*E_];
__device__ float g_K[B_*S_*E_];
__device__ float g_V[B_*S_*E_];
__device__ float g_Vt[B_*H_*D_*S_];   // V transposed: [(b*H+h)][d][s]
__device__ float g_C[B_*S_*E_];

// ===========================================================================
// mma.sync + cp.async helpers (family-portable sm_80+; tcgen05 unavailable:
// harness targets virtual arch compute_100, forbidding accelerated-family PTX)
// ===========================================================================
__device__ __forceinline__ uint32_t smem_u32(const void* p) {
    uint32_t a;
    asm("{ .reg .u64 t; cvta.to.shared.u64 t, %1; cvt.u32.u64 %0, t; }"
        : "=r"(a) : "l"(p));
    return a;
}
__device__ __forceinline__ uint32_t tf32_bits(float a) {
    uint32_t u;
    asm("cvt.rna.tf32.f32 %0, %1;" : "=r"(u) : "f"(a));
    return u;
}
// pack two floats as bf16x2: e0 -> low half, e1 -> high half (PTX: 1st src = hi)
__device__ __forceinline__ uint32_t pack_bf16(float e0, float e1) {
    uint32_t r;
    asm("cvt.rn.bf16x2.f32 %0, %1, %2;" : "=r"(r) : "f"(e1), "f"(e0));
    return r;
}
__device__ __forceinline__ void ldsm4(uint32_t& r0, uint32_t& r1,
                                      uint32_t& r2, uint32_t& r3, uint32_t addr) {
    asm volatile("ldmatrix.sync.aligned.m8n8.x4.shared.b16 {%0,%1,%2,%3}, [%4];"
                 : "=r"(r0), "=r"(r1), "=r"(r2), "=r"(r3) : "r"(addr));
}
__device__ __forceinline__ void mma_tf32(float* c, const uint32_t* a,
                                         uint32_t b0, uint32_t b1) {
    asm volatile("mma.sync.aligned.m16n8k8.row.col.f32.tf32.tf32.f32 "
                 "{%0,%1,%2,%3}, {%4,%5,%6,%7}, {%8,%9}, {%0,%1,%2,%3};"
                 : "+f"(c[0]), "+f"(c[1]), "+f"(c[2]), "+f"(c[3])
                 : "r"(a[0]), "r"(a[1]), "r"(a[2]), "r"(a[3]), "r"(b0), "r"(b1));
}
__device__ __forceinline__ void mma_bf16(float* c, const uint32_t* a,
                                         uint32_t b0, uint32_t b1) {
    asm volatile("mma.sync.aligned.m16n8k16.row.col.f32.bf16.bf16.f32 "
                 "{%0,%1,%2,%3}, {%4,%5,%6,%7}, {%8,%9}, {%0,%1,%2,%3};"
                 : "+f"(c[0]), "+f"(c[1]), "+f"(c[2]), "+f"(c[3])
                 : "r"(a[0]), "r"(a[1]), "r"(a[2]), "r"(a[3]), "r"(b0), "r"(b1));
}
__device__ __forceinline__ void split4(const uint32_t* r, uint32_t* hi, uint32_t* lo) {
    #pragma unroll
    for (int i = 0; i < 4; i++) {
        const float v = __uint_as_float(r[i]);
        hi[i] = tf32_bits(v);
        lo[i] = tf32_bits(v - __uint_as_float(hi[i]));
    }
}
__device__ __forceinline__ void cvt4(const uint32_t* r, uint32_t* hi) {
    #pragma unroll
    for (int i = 0; i < 4; i++) hi[i] = tf32_bits(__uint_as_float(r[i]));
}
__device__ __forceinline__ void cpasync16(uint32_t dst, const void* src) {
    asm volatile("cp.async.cg.shared.global [%0], [%1], 16;" :: "r"(dst), "l"(src));
}
__device__ __forceinline__ void cpasync_commit() {
    asm volatile("cp.async.commit_group;");
}
template<int N> __device__ __forceinline__ void cpasync_wait() {
    asm volatile("cp.async.wait_group %0;" :: "n"(N));
}

// ===========================================================================
// bf16 2-split mma.sync GEMM (NT): C[128x128] = A[M,1024] * Bw[N,1024]^T
// D += Ahi*Bhi + Ahi*Blo + Alo*Bhi  (bf16 hi/lo, error ~2^-17 per product).
// Split ONCE at STS time; packed bf16 pairs; 80-byte rows (20-bank stride
// => every ldmatrix phase hits all 32 banks, conflict-free, no swizzle).
// Ping-pong stages, ONE barrier per K-tile (K-tile = 32).
// ===========================================================================
#define ROWB 80                         // 32 bf16 = 64B + 16B pad
#define TILE_BF (128 * ROWB)            // 10240 B per (hi|lo)x(A|B) tile
#define GSTAGE_B (4 * TILE_BF)          // Ahi|Alo|Bhi|Blo = 40960 B
#define GEMM_SMEM (2 * GSTAGE_B + 128)

__device__ __forceinline__ void tc_gemm_body(const float* __restrict__ A,
                                             const float* __restrict__ Bw,
                                             float* __restrict__ C,
                                             int bm, int bn)
{
    extern __shared__ char smraw[];
    char* smb = (char*)(((uintptr_t)smraw + 127) & ~(uintptr_t)127);
    const uint32_t sbase = smem_u32(smb);

    const int tid  = threadIdx.x;
    const int wid  = tid >> 5;
    const int lane = tid & 31;
    const int wm = (wid >> 2) * 64;
    const int wn = (wid & 3) * 32;

    const int rlbA   = (lane & 7) + ((lane >> 3) & 1) * 8;
    const int col16A = (lane >> 4) & 1;
    const int rlbB   = (lane & 7) + ((lane >> 4) & 1) * 8;
    const int col16B = (lane >> 3) & 1;

    // fragment base offsets (80B rows, no swizzle)
    uint32_t aOff[4], bOff[2];
    #pragma unroll
    for (int f = 0; f < 4; f++) aOff[f] = (wm + f * 16 + rlbA) * ROWB + col16A * 16;
    #pragma unroll
    for (int p = 0; p < 2; p++) bOff[p] = (wn + p * 16 + rlbB) * ROWB + col16B * 16;

    const float* Abase = A  + (size_t)bm * E_;
    const float* Bbase = Bw + (size_t)bn * E_;

    float acc[4][4][4] = {};
    float4 rgA[4], rgB[4];

    // preload k-tile 0
    #pragma unroll
    for (int l = 0; l < 4; l++) {
        const int idx = tid + l * 256;
        const int row = idx >> 3, c4 = idx & 7;
        rgA[l] = *(const float4*)(Abase + (size_t)row * E_ + c4 * 4);
        rgB[l] = *(const float4*)(Bbase + (size_t)row * E_ + c4 * 4);
    }

    for (int kt = 0; kt < 32; kt++) {
        const uint32_t cur = (kt & 1) * GSTAGE_B;
        char* st = smb + cur;

        // ---- split to bf16 hi/lo and STS (once per element) ----
        #pragma unroll
        for (int l = 0; l < 4; l++) {
            const int idx = tid + l * 256;
            const int row = idx >> 3, c4 = idx & 7;
            const int off = row * ROWB + c4 * 8;
            {
                float4 a = rgA[l];
                uint32_t h0 = pack_bf16(a.x, a.y);
                uint32_t h1 = pack_bf16(a.z, a.w);
                float f0 = __uint_as_float(h0 << 16);
                float f1 = __uint_as_float(h0 & 0xffff0000u);
                float f2 = __uint_as_float(h1 << 16);
                float f3 = __uint_as_float(h1 & 0xffff0000u);
                uint32_t l0 = pack_bf16(a.x - f0, a.y - f1);
                uint32_t l1 = pack_bf16(a.z - f2, a.w - f3);
                *(uint2*)(st + off)           = make_uint2(h0, h1);
                *(uint2*)(st + TILE_BF + off) = make_uint2(l0, l1);
            }
            {
                float4 b = rgB[l];
                uint32_t h0 = pack_bf16(b.x, b.y);
                uint32_t h1 = pack_bf16(b.z, b.w);
                float f0 = __uint_as_float(h0 << 16);
                float f1 = __uint_as_float(h0 & 0xffff0000u);
                float f2 = __uint_as_float(h1 << 16);
                float f3 = __uint_as_float(h1 & 0xffff0000u);
                uint32_t l0 = pack_bf16(b.x - f0, b.y - f1);
                uint32_t l1 = pack_bf16(b.z - f2, b.w - f3);
                *(uint2*)(st + 2 * TILE_BF + off) = make_uint2(h0, h1);
                *(uint2*)(st + 3 * TILE_BF + off) = make_uint2(l0, l1);
            }
        }
        __syncthreads();

        // prefetch next k-tile into registers
        if (kt + 1 < 32) {
            const int k0 = (kt + 1) * 32;
            #pragma unroll
            for (int l = 0; l < 4; l++) {
                const int idx = tid + l * 256;
                const int row = idx >> 3, c4 = idx & 7;
                rgA[l] = *(const float4*)(Abase + (size_t)row * E_ + k0 + c4 * 4);
                rgB[l] = *(const float4*)(Bbase + (size_t)row * E_ + k0 + c4 * 4);
            }
        }

        const uint32_t sA = sbase + cur;

        // ---- compute: 2 k16 slices, 3 bf16 streams ----
        #pragma unroll
        for (int s = 0; s < 2; s++) {
            const uint32_t kb = s * 32;
            uint32_t ah[4][4], al[4][4];
            #pragma unroll
            for (int f = 0; f < 4; f++) {
                ldsm4(ah[f][0], ah[f][1], ah[f][2], ah[f][3],
                      sA + aOff[f] + kb);
                ldsm4(al[f][0], al[f][1], al[f][2], al[f][3],
                      sA + TILE_BF + aOff[f] + kb);
            }
            #pragma unroll
            for (int p = 0; p < 2; p++) {
                uint32_t bh[4], bl[4];
                ldsm4(bh[0], bh[1], bh[2], bh[3],
                      sA + 2 * TILE_BF + bOff[p] + kb);
                ldsm4(bl[0], bl[1], bl[2], bl[3],
                      sA + 3 * TILE_BF + bOff[p] + kb);
                #pragma unroll
                for (int gg = 0; gg < 2; gg++) {
                    const int g = p * 2 + gg;
                    const uint32_t b0h = bh[gg * 2], b1h = bh[gg * 2 + 1];
                    const uint32_t b0l = bl[gg * 2], b1l = bl[gg * 2 + 1];
                    #pragma unroll
                    for (int f = 0; f < 4; f++) {
                        mma_bf16(acc[f][g], ah[f], b0h, b1h);
                        mma_bf16(acc[f][g], ah[f], b0l, b1l);
                        mma_bf16(acc[f][g], al[f], b0h, b1h);
                    }
                }
            }
        }
    }

    #pragma unroll
    for (int f = 0; f < 4; f++) {
        const int r0 = bm + wm + f * 16 + (lane >> 2);
        #pragma unroll
        for (int g = 0; g < 4; g++) {
            const int cc = bn + wn + g * 8 + (lane & 3) * 2;
            *(float2*)(C + (size_t)r0 * E_ + cc) =
                make_float2(acc[f][g][0], acc[f][g][1]);
            *(float2*)(C + (size_t)(r0 + 8) * E_ + cc) =
                make_float2(acc[f][g][2], acc[f][g][3]);
        }
    }
}

__global__ __launch_bounds__(256)
void tc_gemm_qkv(const float* __restrict__ x, const float* __restrict__ Wq,
                 const float* __restrict__ Wk, const float* __restrict__ Wv)
{
    const int sel = blockIdx.x >> 3;
    const float* Bw = (sel == 0) ? Wq : (sel == 1) ? Wk : Wv;
    float* C = (sel == 0) ? g_Q : (sel == 1) ? g_K : g_V;
    tc_gemm_body(x, Bw, C, blockIdx.y * 128, (blockIdx.x & 7) * 128);
}

__global__ __launch_bounds__(256)
void tc_gemm_o(const float* __restrict__ Wo, float* __restrict__ out)
{
    tc_gemm_body(g_C, Wo, out, blockIdx.y * 128, blockIdx.x * 128);
}

// ===========================================================================
// V transpose: g_V [b][s][h*64+d] -> g_Vt [(b*H+h)][d][s]  (unchanged)
// ===========================================================================
__global__ __launch_bounds__(256)
void v_transpose()
{
    __shared__ float ts[64 * 65];
    const int st = blockIdx.x;
    const int h = blockIdx.y, b = blockIdx.z;
    const float* Vg = g_V + (size_t)b * S_ * E_ + h * D_;
    float* Vt = g_Vt + (size_t)(b * H_ + h) * D_ * S_;
    const int tid = threadIdx.x;

    #pragma unroll
    for (int l = 0; l < 4; l++) {
        const int idx = tid + l * 256;
        const int s = idx >> 4, c4 = idx & 15;
        float4 v = *(const float4*)(Vg + (size_t)(st * 64 + s) * E_ + c4 * 4);
        ts[(c4 * 4 + 0) * 65 + s] = v.x;
        ts[(c4 * 4 + 1) * 65 + s] = v.y;
        ts[(c4 * 4 + 2) * 65 + s] = v.z;
        ts[(c4 * 4 + 3) * 65 + s] = v.w;
    }
    __syncthreads();
    #pragma unroll
    for (int l = 0; l < 4; l++) {
        const int idx = tid + l * 256;
        const int d = idx >> 4, c4 = idx & 15;
        float4 w = make_float4(ts[d * 65 + c4 * 4 + 0], ts[d * 65 + c4 * 4 + 1],
                               ts[d * 65 + c4 * 4 + 2], ts[d * 65 + c4 * 4 + 3]);
        *(float4*)(Vt + (size_t)d * S_ + st * 64 + c4 * 4) = w;
    }
}

// ===========================================================================
// Flash attention, mma.sync (UNCHANGED from round 10 — passed @ 2.1e-4):
// cp.async 2-stage K/V ring; tf32 3-stream QK, single-stream PV.
// ===========================================================================
#define FST_STAGE 32768                 // per-stage: K raw 16KB + V raw 16KB
#define FST_TOTAL (2 * FST_STAGE + 128)

__device__ __forceinline__ void flash_issue_kv(uint32_t sdst,
                                               const float* __restrict__ Kg,
                                               const float* __restrict__ Vtg,
                                               int jt, int tid)
{
    #pragma unroll
    for (int l = 0; l < 4; l++) {
        const int idx = tid + l * 256;
        const int row = idx >> 4, c4 = idx & 15;
        const int off = (c4 >> 3) * 8192 + row * 128 +
                        (((c4 & 7) * 16) ^ ((row & 7) << 4));
        cpasync16(sdst + off,         Kg + (size_t)(jt * 64 + row) * E_ + c4 * 4);
        cpasync16(sdst + 16384 + off, Vtg + (size_t)row * S_ + jt * 64 + c4 * 4);
    }
    cpasync_commit();
}

__global__ __launch_bounds__(256)
void flash_mma()
{
    extern __shared__ char fraw[];
    char* fsm = (char*)(((uintptr_t)fraw + 127) & ~(uintptr_t)127);
    const uint32_t sb = smem_u32(fsm);

    const int tid = threadIdx.x, wid = tid >> 5, lane = tid & 31;
    const int qt = (S_ / 128 - 1) - (int)blockIdx.x;   // heavy tiles first
    const int h = blockIdx.y, b = blockIdx.z;

    const float* Qg  = g_Q + (size_t)b * S_ * E_ + h * D_;
    const float* Kg  = g_K + (size_t)b * S_ * E_ + h * D_;
    const float* Vtg = g_Vt + (size_t)(b * H_ + h) * D_ * S_;
    float* Og = g_C + (size_t)b * S_ * E_ + h * D_;

    const int rlbA = (lane & 7) + ((lane >> 3) & 1) * 8;
    const int c16A = (lane >> 4) & 1;
    const int rlbB = (lane & 7) + ((lane >> 4) & 1) * 8;
    const int c16B = (lane >> 3) & 1;
    const uint32_t aX = ((rlbA & 7) << 4) ^ (c16A * 16);
    const uint32_t bX = ((rlbB & 7) << 4) ^ (c16B * 16);
    const int wq = wid * 16;
    const uint32_t rA = wq + rlbA;
    uint32_t bR[4];
    #pragma unroll
    for (int p = 0; p < 4; p++) bR[p] = (p * 16 + rlbB) * 128;

    const int qq   = lane & 3;
    const int srcA = (lane & ~3) | (qq >> 1);
    const int srcB = srcA + 2;
    const int selo = qq & 1;

    // prologue: KV tile 0 in flight; stage Q raw through stage-1 buffer
    flash_issue_kv(sb, Kg, Vtg, 0, tid);
    #pragma unroll
    for (int l = 0; l < 8; l++) {
        const int idx = tid + l * 256;
        const int row = idx >> 4, c4 = idx & 15;
        float4 q = *(const float4*)(Qg + (size_t)(qt * 128 + row) * E_ + c4 * 4);
        const int off = FST_STAGE + (c4 >> 3) * 16384 + row * 128 +
                        (((c4 & 7) * 16) ^ ((row & 7) << 4));
        *(float4*)(fsm + off) = q;
    }
    __syncthreads();
    uint32_t qr[8][4];
    #pragma unroll
    for (int s = 0; s < 8; s++) {
        const uint32_t ad = FST_STAGE + (s >> 2) * 16384 + rA * 128 +
                            (((s & 3) * 32) ^ aX);
        ldsm4(qr[s][0], qr[s][1], qr[s][2], qr[s][3], sb + ad);
    }
    __syncthreads();

    float o[8][4] = {};
    float mrow[2] = {NEGINF, NEGINF};
    float lrow[2] = {0.0f, 0.0f};

    const int nj = 2 * qt + 2;
    for (int jt = 0; jt < nj; jt++) {
        cpasync_wait<0>();
        __syncthreads();

        if (jt + 1 < nj)
            flash_issue_kv(sb + ((jt + 1) & 1) * FST_STAGE, Kg, Vtg, jt + 1, tid);

        const uint32_t cur = (jt & 1) * FST_STAGE;

        float sc[8][4] = {};
        #pragma unroll
        for (int s = 0; s < 8; s++) {
            const uint32_t cof = cur + (s >> 2) * 8192;
            const uint32_t colb = (s & 3) * 32;
            uint32_t qh[4], ql[4];
            split4(qr[s], qh, ql);
            uint32_t kh[4][4], kl[4][4];
            #pragma unroll
            for (int p = 0; p < 4; p++) {
                uint32_t kr[4];
                ldsm4(kr[0], kr[1], kr[2], kr[3], sb + cof + bR[p] + (colb ^ bX));
                split4(kr, kh[p], kl[p]);
            }
            #pragma unroll
            for (int nt = 0; nt < 8; nt++) {
                const uint32_t b0h = kh[nt >> 1][(nt & 1) * 2];
                const uint32_t b1h = kh[nt >> 1][(nt & 1) * 2 + 1];
                const uint32_t b0l = kl[nt >> 1][(nt & 1) * 2];
                const uint32_t b1l = kl[nt >> 1][(nt & 1) * 2 + 1];
                mma_tf32(sc[nt], qh, b0h, b1h);
                mma_tf32(sc[nt], qh, b0l, b1l);
                mma_tf32(sc[nt], ql, b0h, b1h);
            }
        }

        const bool maskt = (jt >= 2 * qt);
        const int qr1 = qt * 128 + wq + (lane >> 2);
        const int kcb = jt * 64 + 2 * (lane & 3);
        #pragma unroll
        for (int ri = 0; ri < 2; ri++) {
            const int qrow = qr1 + ri * 8;
            float mx = NEGINF;
            #pragma unroll
            for (int nt = 0; nt < 8; nt++) {
                float s0 = sc[nt][2 * ri] * 8.0f;
                float s1 = sc[nt][2 * ri + 1] * 8.0f;
                if (maskt) {
                    const int c = kcb + nt * 8;
                    if (c > qrow)     s0 = NEGINF;
                    if (c + 1 > qrow) s1 = NEGINF;
                }
                sc[nt][2 * ri]     = s0;
                sc[nt][2 * ri + 1] = s1;
                mx = fmaxf(mx, fmaxf(s0, s1));
            }
            mx = fmaxf(mx, __shfl_xor_sync(0xffffffffu, mx, 1));
            mx = fmaxf(mx, __shfl_xor_sync(0xffffffffu, mx, 2));
            const float mnew = fmaxf(mrow[ri], mx);
            const float alpha = __expf(mrow[ri] - mnew);
            float sum = 0.0f;
            #pragma unroll
            for (int nt = 0; nt < 8; nt++) {
                const float p0 = __expf(sc[nt][2 * ri] - mnew);
                const float p1 = __expf(sc[nt][2 * ri + 1] - mnew);
                sc[nt][2 * ri] = p0; sc[nt][2 * ri + 1] = p1;
                sum += p0 + p1;
                o[nt][2 * ri]     *= alpha;
                o[nt][2 * ri + 1] *= alpha;
            }
            sum += __shfl_xor_sync(0xffffffffu, sum, 1);
            sum += __shfl_xor_sync(0xffffffffu, sum, 2);
            lrow[ri] = lrow[ri] * alpha + sum;
            mrow[ri] = mnew;
        }

        #pragma unroll
        for (int kk = 0; kk < 8; kk++) {
            float v00 = __shfl_sync(0xffffffffu, sc[kk][0], srcA);
            float v01 = __shfl_sync(0xffffffffu, sc[kk][1], srcA);
            float v10 = __shfl_sync(0xffffffffu, sc[kk][0], srcB);
            float v11 = __shfl_sync(0xffffffffu, sc[kk][1], srcB);
            float w00 = __shfl_sync(0xffffffffu, sc[kk][2], srcA);
            float w01 = __shfl_sync(0xffffffffu, sc[kk][3], srcA);
            float w10 = __shfl_sync(0xffffffffu, sc[kk][2], srcB);
            float w11 = __shfl_sync(0xffffffffu, sc[kk][3], srcB);
            uint32_t ph[4];
            ph[0] = tf32_bits(selo ? v01 : v00);
            ph[1] = tf32_bits(selo ? w01 : w00);
            ph[2] = tf32_bits(selo ? v11 : v10);
            ph[3] = tf32_bits(selo ? w11 : w10);

            const uint32_t cof = cur + 16384 + (kk >> 2) * 8192;
            const uint32_t colb = (kk & 3) * 32;
            uint32_t vh[4][4];
            #pragma unroll
            for (int p = 0; p < 4; p++) {
                uint32_t vr[4];
                ldsm4(vr[0], vr[1], vr[2], vr[3], sb + cof + bR[p] + (colb ^ bX));
                cvt4(vr, vh[p]);
            }
            #pragma unroll
            for (int nt = 0; nt < 8; nt++)
                mma_tf32(o[nt], ph, vh[nt >> 1][(nt & 1) * 2],
                                    vh[nt >> 1][(nt & 1) * 2 + 1]);
        }
    }

    const float inv0 = 1.0f / lrow[0];
    const float inv1 = 1.0f / lrow[1];
    const int gr1 = qt * 128 + wq + (lane >> 2);
    #pragma unroll
    for (int nt = 0; nt < 8; nt++) {
        const int col = nt * 8 + 2 * (lane & 3);
        *(float2*)(Og + (size_t)gr1 * E_ + col) =
            make_float2(o[nt][0] * inv0, o[nt][1] * inv0);
        *(float2*)(Og + (size_t)(gr1 + 8) * E_ + col) =
            make_float2(o[nt][2] * inv1, o[nt][3] * inv1);
    }
}

// ===========================================================================
extern "C" void kernel_launch(void* const* d_in, const int* in_sizes, int n_in,
                              void* d_out, int out_size)
{
    const float* x  = (const float*)d_in[0];
    const float* Wq = (const float*)d_in[1];
    const float* Wk = (const float*)d_in[2];
    const float* Wv = (const float*)d_in[3];
    const float* Wo = (const float*)d_in[4];
    float* out = (float*)d_out;

    cudaFuncSetAttribute(tc_gemm_qkv, cudaFuncAttributeMaxDynamicSharedMemorySize, GEMM_SMEM);
    cudaFuncSetAttribute(tc_gemm_o,   cudaFuncAttributeMaxDynamicSharedMemorySize, GEMM_SMEM);
    cudaFuncSetAttribute(flash_mma,   cudaFuncAttributeMaxDynamicSharedMemorySize, FST_TOTAL);

    dim3 gq(24, 32);
    tc_gemm_qkv<<<gq, 256, GEMM_SMEM>>>(x, Wq, Wk, Wv);

    dim3 gt(32, 16, 2);
    v_transpose<<<gt, 256>>>();

    dim3 ga(S_ / 128, H_, B_);
    flash_mma<<<ga, 256, FST_TOTAL>>>();

    dim3 go(8, 32);
    tc_gemm_o<<<go, 256, GEMM_SMEM>>>(Wo, out);
}